// round 13
// baseline (speedup 1.0000x reference)
#include <cuda_runtime.h>
#include <math.h>

#define BATCH   4
#define N_SEQ   1024
#define D_MODEL 256
#define N_HEADS 8
#define D_HEAD  32
#define ATT_SCALE 0.17677669529663687f   // 1/sqrt(32)

// Scratch (device globals: no allocation allowed in kernel_launch)
__device__ float g_Q[BATCH * N_HEADS * N_SEQ * D_HEAD];   // [b,h,n,dk]  tf32, pre-scaled
__device__ float g_K[BATCH * N_HEADS * N_SEQ * D_HEAD];   // tf32-rounded
__device__ float g_V[BATCH * N_HEADS * N_SEQ * D_HEAD];   // tf32-rounded
__device__ float g_AO[BATCH * N_SEQ * D_MODEL];           // attention out, tf32-rounded
__device__ float g_maskval[BATCH * N_SEQ];                // 0 or -inf per key
__device__ float g_X[BATCH * N_SEQ * D_MODEL];            // x, tf32-rounded
__device__ float g_W4[4 * D_MODEL * D_MODEL];             // Wq,Wk,Wv,Wo tf32-rounded

__device__ __forceinline__ unsigned f2tf32(float f) {
    unsigned u;
    asm("cvt.rna.tf32.f32 %0, %1;" : "=r"(u) : "f"(f));
    return u;
}
__device__ __forceinline__ float rnd_tf32(float f) {
    return __uint_as_float(f2tf32(f));
}

#define MMA_TF32(d, a, b)                                                     \
    asm volatile(                                                             \
        "mma.sync.aligned.m16n8k8.row.col.f32.tf32.tf32.f32 "                 \
        "{%0,%1,%2,%3}, {%4,%5,%6,%7}, {%8,%9}, {%0,%1,%2,%3};\n"             \
        : "+f"((d)[0]), "+f"((d)[1]), "+f"((d)[2]), "+f"((d)[3])              \
        : "r"((a)[0]), "r"((a)[1]), "r"((a)[2]), "r"((a)[3]),                 \
          "r"((b)[0]), "r"((b)[1]))

__device__ __forceinline__ void cp_async16(void* s, const void* g) {
    unsigned sa = (unsigned)__cvta_generic_to_shared(s);
    asm volatile("cp.async.cg.shared.global [%0], [%1], 16;" :: "r"(sa), "l"(g));
}
#define CP_COMMIT() asm volatile("cp.async.commit_group;")
#define CP_WAIT0()  asm volatile("cp.async.wait_group 0;")
#define CP_WAIT1()  asm volatile("cp.async.wait_group 1;")

// ---------------------------------------------------------------------------
// Prep: tf32-round x and all four weight matrices into scratch; expand mask.
// grid=96, block=256.
// ---------------------------------------------------------------------------
__global__ void prep_kernel(
    const float* __restrict__ x,
    const float* __restrict__ Wq, const float* __restrict__ Wk,
    const float* __restrict__ Wv, const float* __restrict__ Wo,
    const void* __restrict__ mraw)
{
    const int gt = blockIdx.x * blockDim.x + threadIdx.x;
    const int stride = gridDim.x * blockDim.x;

    // x: 1048576 floats = 262144 float4
    for (int i = gt; i < 262144; i += stride) {
        float4 v = ((const float4*)x)[i];
        v.x = rnd_tf32(v.x); v.y = rnd_tf32(v.y);
        v.z = rnd_tf32(v.z); v.w = rnd_tf32(v.w);
        ((float4*)g_X)[i] = v;
    }
    // weights: 4 x 65536 floats = 4 x 16384 float4
    const float* Ws[4] = { Wq, Wk, Wv, Wo };
#pragma unroll
    for (int z = 0; z < 4; z++) {
        const float4* src = (const float4*)Ws[z];
        float4* dst = (float4*)(g_W4 + z * 65536);
        for (int i = gt; i < 16384; i += stride) {
            float4 v = src[i];
            v.x = rnd_tf32(v.x); v.y = rnd_tf32(v.y);
            v.z = rnd_tf32(v.z); v.w = rnd_tf32(v.w);
            dst[i] = v;
        }
    }
    // mask (block 0 only)
    if (blockIdx.x == 0) {
        const int tid = threadIdx.x;
        const unsigned* mi = (const unsigned*)mraw;
        int ok_int = 1, ok_float = 1;
        for (int i = tid; i < 1024; i += 256) {
            unsigned v = mi[i];
            if (v > 1u) ok_int = 0;
            if (v != 0u && v != 0x3F800000u) ok_float = 0;
        }
        int all_int   = __syncthreads_and(ok_int);
        int all_float = __syncthreads_and(ok_float);
        const int mode = all_int ? 0 : (all_float ? 1 : 2);
        const float NEG_INF = __int_as_float(0xff800000);
        for (int i = tid; i < BATCH * N_SEQ; i += 256) {
            int masked;
            if (mode == 0)      masked = ((const int*)mraw)[i] != 0;
            else if (mode == 1) masked = ((const unsigned*)mraw)[i] != 0u;
            else                masked = ((const unsigned char*)mraw)[i] != 0;
            g_maskval[i] = masked ? NEG_INF : 0.0f;
        }
    }
}

// ---------------------------------------------------------------------------
// QKV projection (round-9 structure, pre-rounded inputs -> NO cvt in loop).
// grid=(32,4,3), block=256, tile 128x64.
// ---------------------------------------------------------------------------
#define GEMM_SMEM_BYTES (13824 * 4)

__global__ __launch_bounds__(256) void gemm_qkv_tc(
    const float* __restrict__ bq, const float* __restrict__ bk, const float* __restrict__ bv)
{
    extern __shared__ float sm[];
    float* As = sm;            // [2][128][36]
    float* Ws = sm + 9216;     // [2][64][36]

    const int z = blockIdx.z;
    const float* W    = g_W4 + z * 65536;
    const float* bias = (z == 0) ? bq : (z == 1) ? bk : bv;
    float* out        = (z == 0) ? g_Q : (z == 1) ? g_K : g_V;

    const int tid  = threadIdx.x;
    const int lane = tid & 31;
    const int w    = tid >> 5;
    const int g    = lane >> 2;
    const int t    = lane & 3;
    const int w16  = w * 16;
    const int rbase = blockIdx.x * 128;
    const int cbase = blockIdx.y * 64;

    float sc[8][4];
#pragma unroll
    for (int n = 0; n < 8; n++)
#pragma unroll
        for (int j = 0; j < 4; j++) sc[n][j] = 0.0f;

    auto prefetch = [&](int c) {
        const int k0 = c * 32, st = c & 1;
        float* Ap = As + st * 4608;
        float* Wp = Ws + st * 2304;
#pragma unroll
        for (int it = 0; it < 4; it++) {
            int s = it * 256 + tid;
            int row = s >> 3;
            int c4 = (s & 7) * 4;
            cp_async16(&Ap[row * 36 + c4], &g_X[(size_t)(rbase + row) * D_MODEL + k0 + c4]);
        }
#pragma unroll
        for (int it = 0; it < 2; it++) {
            int s = it * 256 + tid;
            int row = s >> 3;
            int c4 = (s & 7) * 4;
            cp_async16(&Wp[row * 36 + c4], &W[(size_t)(cbase + row) * D_MODEL + k0 + c4]);
        }
        CP_COMMIT();
    };

    prefetch(0);
    for (int c = 0; c < 8; c++) {
        const int st = c & 1;
        const float* Ap = As + st * 4608;
        const float* Wp = Ws + st * 2304;
        if (c < 7) { prefetch(c + 1); CP_WAIT1(); }
        else       { CP_WAIT0(); }
        __syncthreads();

        unsigned qa[4][4];
#pragma unroll
        for (int kk = 0; kk < 4; kk++) {
            qa[kk][0] = __float_as_uint(Ap[(w16 + g    ) * 36 + kk * 8 + t    ]);
            qa[kk][1] = __float_as_uint(Ap[(w16 + g + 8) * 36 + kk * 8 + t    ]);
            qa[kk][2] = __float_as_uint(Ap[(w16 + g    ) * 36 + kk * 8 + t + 4]);
            qa[kk][3] = __float_as_uint(Ap[(w16 + g + 8) * 36 + kk * 8 + t + 4]);
        }
#pragma unroll
        for (int n8 = 0; n8 < 8; n8++) {
#pragma unroll
            for (int kk = 0; kk < 4; kk++) {
                unsigned bb[2];
                bb[0] = __float_as_uint(Wp[(n8 * 8 + g) * 36 + kk * 8 + t    ]);
                bb[1] = __float_as_uint(Wp[(n8 * 8 + g) * 36 + kk * 8 + t + 4]);
                MMA_TF32(sc[n8], qa[kk], bb);
            }
        }
        __syncthreads();
    }

    const float scale = (z == 0) ? ATT_SCALE : 1.0f;
#pragma unroll
    for (int n8 = 0; n8 < 8; n8++) {
        int c0 = cbase + n8 * 8 + 2 * t;
        float b0v = bias[c0], b1v = bias[c0 + 1];
        int r0 = rbase + w16 + g;
        int r1 = r0 + 8;
        float2 v0, v1;
        v0.x = rnd_tf32((sc[n8][0] + b0v) * scale);
        v0.y = rnd_tf32((sc[n8][1] + b1v) * scale);
        v1.x = rnd_tf32((sc[n8][2] + b0v) * scale);
        v1.y = rnd_tf32((sc[n8][3] + b1v) * scale);
        int h = c0 >> 5, dk = c0 & 31;
        int b0i = r0 >> 10, n0 = r0 & 1023;
        int b1i = r1 >> 10, n1 = r1 & 1023;
        *(float2*)&out[(size_t)(((b0i << 3) + h) * N_SEQ + n0) * D_HEAD + dk] = v0;
        *(float2*)&out[(size_t)(((b1i << 3) + h) * N_SEQ + n1) * D_HEAD + dk] = v1;
    }
}

// ---------------------------------------------------------------------------
// Output projection (pre-rounded A and W -> NO cvt). grid=(32,4), block=256.
// ---------------------------------------------------------------------------
__global__ __launch_bounds__(256) void gemm_o_tc(
    const float* __restrict__ bias, float* __restrict__ out)
{
    extern __shared__ float sm[];
    float* As = sm;
    float* Ws = sm + 9216;
    const float* W = g_W4 + 3 * 65536;

    const int tid  = threadIdx.x;
    const int lane = tid & 31;
    const int w    = tid >> 5;
    const int g    = lane >> 2;
    const int t    = lane & 3;
    const int w16  = w * 16;
    const int rbase = blockIdx.x * 128;
    const int cbase = blockIdx.y * 64;

    float sc[8][4];
#pragma unroll
    for (int n = 0; n < 8; n++)
#pragma unroll
        for (int j = 0; j < 4; j++) sc[n][j] = 0.0f;

    auto prefetch = [&](int c) {
        const int k0 = c * 32, st = c & 1;
        float* Ap = As + st * 4608;
        float* Wp = Ws + st * 2304;
#pragma unroll
        for (int it = 0; it < 4; it++) {
            int s = it * 256 + tid;
            int row = s >> 3;
            int c4 = (s & 7) * 4;
            cp_async16(&Ap[row * 36 + c4], &g_AO[(size_t)(rbase + row) * D_MODEL + k0 + c4]);
        }
#pragma unroll
        for (int it = 0; it < 2; it++) {
            int s = it * 256 + tid;
            int row = s >> 3;
            int c4 = (s & 7) * 4;
            cp_async16(&Wp[row * 36 + c4], &W[(size_t)(cbase + row) * D_MODEL + k0 + c4]);
        }
        CP_COMMIT();
    };

    prefetch(0);
    for (int c = 0; c < 8; c++) {
        const int st = c & 1;
        const float* Ap = As + st * 4608;
        const float* Wp = Ws + st * 2304;
        if (c < 7) { prefetch(c + 1); CP_WAIT1(); }
        else       { CP_WAIT0(); }
        __syncthreads();

        unsigned qa[4][4];
#pragma unroll
        for (int kk = 0; kk < 4; kk++) {
            qa[kk][0] = __float_as_uint(Ap[(w16 + g    ) * 36 + kk * 8 + t    ]);
            qa[kk][1] = __float_as_uint(Ap[(w16 + g + 8) * 36 + kk * 8 + t    ]);
            qa[kk][2] = __float_as_uint(Ap[(w16 + g    ) * 36 + kk * 8 + t + 4]);
            qa[kk][3] = __float_as_uint(Ap[(w16 + g + 8) * 36 + kk * 8 + t + 4]);
        }
#pragma unroll
        for (int n8 = 0; n8 < 8; n8++) {
#pragma unroll
            for (int kk = 0; kk < 4; kk++) {
                unsigned bb[2];
                bb[0] = __float_as_uint(Wp[(n8 * 8 + g) * 36 + kk * 8 + t    ]);
                bb[1] = __float_as_uint(Wp[(n8 * 8 + g) * 36 + kk * 8 + t + 4]);
                MMA_TF32(sc[n8], qa[kk], bb);
            }
        }
        __syncthreads();
    }

#pragma unroll
    for (int n8 = 0; n8 < 8; n8++) {
        int c0 = cbase + n8 * 8 + 2 * t;
        float b0v = bias[c0], b1v = bias[c0 + 1];
        int r0 = rbase + w16 + g;
        int r1 = r0 + 8;
        float2 v0, v1;
        v0.x = sc[n8][0] + b0v;  v0.y = sc[n8][1] + b1v;
        v1.x = sc[n8][2] + b0v;  v1.y = sc[n8][3] + b1v;
        *(float2*)&out[(size_t)r0 * D_MODEL + c0] = v0;
        *(float2*)&out[(size_t)r1 * D_MODEL + c0] = v1;
    }
}

// ---------------------------------------------------------------------------
// Tensor-core flash attention — round-9 config with ONE change: next-tile
// cp.async issue hoisted ABOVE the softmax (overlaps exp/shfl with loads).
// grid=(16,32), block=128 (4 warps), 108.5 KB dynamic smem -> 2 CTAs/SM.
// ---------------------------------------------------------------------------
#define ATTN_SMEM_BYTES (27136 * 4)

__global__ __launch_bounds__(128) void attn_tc_kernel(
    const float* __restrict__ edge,
    const float* __restrict__ spat,
    const float* __restrict__ rnk)
{
    extern __shared__ float dsm[];
    float* KsB = dsm;                 // 2 * 64*36
    float* VsB = dsm + 4608;          // 2 * 64*40
    float* Ps  = dsm + 9728;          // 64*68
    float* BE  = dsm + 14080;         // 64*68
    float* BS  = BE + 4352;
    float* BR  = BS + 4352;

    const int tid  = threadIdx.x;
    const int lane = tid & 31;
    const int w    = tid >> 5;
    const int g    = lane >> 2;
    const int t    = lane & 3;
    const int qb   = blockIdx.x * 64;
    const int bh   = blockIdx.y;
    const int b    = bh >> 3;
    const int h    = bh & 7;
    const int w16  = w * 16;

    const float* Kg0 = g_K + (size_t)bh * N_SEQ * D_HEAD;
    const float* Vg0 = g_V + (size_t)bh * N_SEQ * D_HEAD;
    const float* maskp = g_maskval + b * N_SEQ;
    const float* eg0 = edge + ((size_t)bh * N_SEQ + qb) * N_SEQ;
    const float* sg0 = spat + ((size_t)bh * N_SEQ + qb) * N_SEQ;
    const float* rg0 = rnk  + ((size_t)bh * N_SEQ + qb) * N_SEQ;

    // issue K/V(0) + bias(0) as one group
    {
#pragma unroll
        for (int it = 0; it < 4; it++) {
            int s = it * 128 + tid;
            int row = s >> 3;
            int c4 = (s & 7) * 4;
            cp_async16(&KsB[row * 36 + c4], &Kg0[row * D_HEAD + c4]);
            cp_async16(&VsB[row * 40 + c4], &Vg0[row * D_HEAD + c4]);
        }
#pragma unroll
        for (int it = 0; it < 8; it++) {
            int s = it * 128 + tid;
            int row = s >> 4;
            int c4 = (s & 15) * 4;
            size_t go = (size_t)row * N_SEQ + c4;
            int so = row * 68 + c4;
            cp_async16(&BE[so], &eg0[go]);
            cp_async16(&BS[so], &sg0[go]);
            cp_async16(&BR[so], &rg0[go]);
        }
        CP_COMMIT();
    }

    // stage Q through Ps, extract fragments
    const float* Qg = g_Q + ((size_t)bh * N_SEQ + qb) * D_HEAD;
#pragma unroll
    for (int it = 0; it < 4; it++) {
        int s = it * 128 + tid;
        int row = s >> 3;
        int c4 = (s & 7) * 4;
        cp_async16(&Ps[row * 68 + c4], &Qg[row * D_HEAD + c4]);
    }
    CP_COMMIT();
    CP_WAIT0();
    __syncthreads();

    unsigned qa[4][4];
#pragma unroll
    for (int kk = 0; kk < 4; kk++) {
        qa[kk][0] = __float_as_uint(Ps[(w16 + g    ) * 68 + kk * 8 + t    ]);
        qa[kk][1] = __float_as_uint(Ps[(w16 + g + 8) * 68 + kk * 8 + t    ]);
        qa[kk][2] = __float_as_uint(Ps[(w16 + g    ) * 68 + kk * 8 + t + 4]);
        qa[kk][3] = __float_as_uint(Ps[(w16 + g + 8) * 68 + kk * 8 + t + 4]);
    }

    // mask regs for tile 0
    float2 mkc[8];
#pragma unroll
    for (int n8 = 0; n8 < 8; n8++)
        mkc[n8] = *(const float2*)&maskp[n8 * 8 + 2 * t];

    float o[4][4];
#pragma unroll
    for (int n = 0; n < 4; n++)
#pragma unroll
        for (int j = 0; j < 4; j++) o[n][j] = 0.0f;

    float m0 = __int_as_float(0xff800000), m1 = m0;
    float l0 = 0.0f, l1 = 0.0f;

    for (int i = 0; i < 16; i++) {
        const int kb = i * 64;
        const int cur = i & 1;
        float* Ks = KsB + cur * 2304;
        float* Vs = VsB + cur * 2560;

        // 1. group(i) arrived; every warp finished tile i-1 entirely
        CP_WAIT0();
        __syncthreads();

        // 2. S = Q K^T (Q pre-scaled by ATT_SCALE)
        float sc[8][4];
#pragma unroll
        for (int n8 = 0; n8 < 8; n8++) {
            sc[n8][0] = sc[n8][1] = sc[n8][2] = sc[n8][3] = 0.0f;
#pragma unroll
            for (int kk = 0; kk < 4; kk++) {
                unsigned bb[2];
                bb[0] = __float_as_uint(Ks[(n8 * 8 + g) * 36 + kk * 8 + t    ]);
                bb[1] = __float_as_uint(Ks[(n8 * 8 + g) * 36 + kk * 8 + t + 4]);
                MMA_TF32(sc[n8], qa[kk], bb);
            }
        }

        // 3. combine biases (from smem stage) + mask (regs)
#pragma unroll
        for (int n8 = 0; n8 < 8; n8++) {
            int c0 = n8 * 8 + 2 * t;
            int ro0 = (w16 + g    ) * 68 + c0;
            int ro1 = (w16 + g + 8) * 68 + c0;
            float2 e0 = *(float2*)&BE[ro0], e1 = *(float2*)&BE[ro1];
            float2 s0 = *(float2*)&BS[ro0], s1 = *(float2*)&BS[ro1];
            float2 r0 = *(float2*)&BR[ro0], r1 = *(float2*)&BR[ro1];
            float2 mk = mkc[n8];
            sc[n8][0] += (e0.x + s0.x) + (r0.x + mk.x);
            sc[n8][1] += (e0.y + s0.y) + (r0.y + mk.y);
            sc[n8][2] += (e1.x + s1.x) + (r1.x + mk.x);
            sc[n8][3] += (e1.y + s1.y) + (r1.y + mk.y);
        }

        // 4. all warps done reading bias stage + Ks -> refill NOW (hoisted
        //    above softmax so exp/shfl overlap the loads)
        __syncthreads();
        if (i < 15) {
            const int kbn = kb + 64;
            const int alt = 1 - cur;
            const float* Kg = Kg0 + (size_t)kbn * D_HEAD;
            const float* Vg = Vg0 + (size_t)kbn * D_HEAD;
            float* Ka = KsB + alt * 2304;
            float* Va = VsB + alt * 2560;
#pragma unroll
            for (int it = 0; it < 4; it++) {
                int s = it * 128 + tid;
                int row = s >> 3;
                int c4 = (s & 7) * 4;
                cp_async16(&Ka[row * 36 + c4], &Kg[row * D_HEAD + c4]);
                cp_async16(&Va[row * 40 + c4], &Vg[row * D_HEAD + c4]);
            }
            const float* eg = eg0 + kbn;
            const float* sg = sg0 + kbn;
            const float* rg = rg0 + kbn;
#pragma unroll
            for (int it = 0; it < 8; it++) {
                int s = it * 128 + tid;
                int row = s >> 4;
                int c4 = (s & 15) * 4;
                size_t go = (size_t)row * N_SEQ + c4;
                int so = row * 68 + c4;
                cp_async16(&BE[so], &eg[go]);
                cp_async16(&BS[so], &sg[go]);
                cp_async16(&BR[so], &rg[go]);
            }
            CP_COMMIT();
#pragma unroll
            for (int n8 = 0; n8 < 8; n8++)
                mkc[n8] = *(const float2*)&maskp[kbn + n8 * 8 + 2 * t];
        }

        // 5. online softmax (overlaps the in-flight group)
        float ml0 = sc[0][0], ml1 = sc[0][2];
#pragma unroll
        for (int n8 = 0; n8 < 8; n8++) {
            ml0 = fmaxf(ml0, fmaxf(sc[n8][0], sc[n8][1]));
            ml1 = fmaxf(ml1, fmaxf(sc[n8][2], sc[n8][3]));
        }
        ml0 = fmaxf(ml0, __shfl_xor_sync(0xffffffffu, ml0, 1));
        ml0 = fmaxf(ml0, __shfl_xor_sync(0xffffffffu, ml0, 2));
        ml1 = fmaxf(ml1, __shfl_xor_sync(0xffffffffu, ml1, 1));
        ml1 = fmaxf(ml1, __shfl_xor_sync(0xffffffffu, ml1, 2));

        float mn0 = fmaxf(m0, ml0);
        float mn1 = fmaxf(m1, ml1);
        float mc0 = fmaxf(mn0, -1e30f);
        float mc1 = fmaxf(mn1, -1e30f);
        float rs0 = __expf(fmaxf(m0, -1e30f) - mc0);
        float rs1 = __expf(fmaxf(m1, -1e30f) - mc1);
        m0 = mn0; m1 = mn1;

        float sum0 = 0.0f, sum1 = 0.0f;
#pragma unroll
        for (int n8 = 0; n8 < 8; n8++) {
            float p0 = __expf(sc[n8][0] - mc0);
            float p1 = __expf(sc[n8][1] - mc0);
            float p2 = __expf(sc[n8][2] - mc1);
            float p3 = __expf(sc[n8][3] - mc1);
            sum0 += p0 + p1;
            sum1 += p2 + p3;
            float2 w0, w1;
            w0.x = rnd_tf32(p0); w0.y = rnd_tf32(p1);
            w1.x = rnd_tf32(p2); w1.y = rnd_tf32(p3);
            *(float2*)&Ps[(w16 + g    ) * 68 + n8 * 8 + 2 * t] = w0;
            *(float2*)&Ps[(w16 + g + 8) * 68 + n8 * 8 + 2 * t] = w1;
        }
        sum0 += __shfl_xor_sync(0xffffffffu, sum0, 1);
        sum0 += __shfl_xor_sync(0xffffffffu, sum0, 2);
        sum1 += __shfl_xor_sync(0xffffffffu, sum1, 1);
        sum1 += __shfl_xor_sync(0xffffffffu, sum1, 2);
        l0 = l0 * rs0 + sum0;
        l1 = l1 * rs1 + sum1;

#pragma unroll
        for (int n = 0; n < 4; n++) {
            o[n][0] *= rs0; o[n][1] *= rs0;
            o[n][2] *= rs1; o[n][3] *= rs1;
        }

        __syncwarp();   // this warp's Ps rows visible warp-wide

        // 6. O += P V
#pragma unroll
        for (int kk = 0; kk < 8; kk++) {
            unsigned pa[4];
            pa[0] = __float_as_uint(Ps[(w16 + g    ) * 68 + kk * 8 + t    ]);
            pa[1] = __float_as_uint(Ps[(w16 + g + 8) * 68 + kk * 8 + t    ]);
            pa[2] = __float_as_uint(Ps[(w16 + g    ) * 68 + kk * 8 + t + 4]);
            pa[3] = __float_as_uint(Ps[(w16 + g + 8) * 68 + kk * 8 + t + 4]);
#pragma unroll
            for (int n = 0; n < 4; n++) {
                unsigned bb[2];
                bb[0] = __float_as_uint(Vs[(kk * 8 + t    ) * 40 + n * 8 + g]);
                bb[1] = __float_as_uint(Vs[(kk * 8 + t + 4) * 40 + n * 8 + g]);
                MMA_TF32(o[n], pa, bb);
            }
        }
    }

    // normalize + scatter (tf32-rounded for the O-projection mma)
    float inv0 = (l0 > 0.0f) ? (1.0f / l0) : 0.0f;
    float inv1 = (l1 > 0.0f) ? (1.0f / l1) : 0.0f;
    const int r0 = qb + w16 + g;
    const int r1 = r0 + 8;
#pragma unroll
    for (int n = 0; n < 4; n++) {
        int d = n * 8 + 2 * t;
        float2 v0, v1;
        v0.x = rnd_tf32(o[n][0] * inv0);
        v0.y = rnd_tf32(o[n][1] * inv0);
        v1.x = rnd_tf32(o[n][2] * inv1);
        v1.y = rnd_tf32(o[n][3] * inv1);
        *(float2*)&g_AO[((size_t)(b * N_SEQ + r0)) * D_MODEL + h * D_HEAD + d] = v0;
        *(float2*)&g_AO[((size_t)(b * N_SEQ + r1)) * D_MODEL + h * D_HEAD + d] = v1;
    }
}

// ---------------------------------------------------------------------------
extern "C" void kernel_launch(void* const* d_in, const int* in_sizes, int n_in,
                              void* d_out, int out_size)
{
    const float* x    = (const float*)d_in[0];
    const float* edge = (const float*)d_in[1];
    const float* spat = (const float*)d_in[2];
    const float* rnk  = (const float*)d_in[3];
    const void*  mask = d_in[4];
    const float* Wq = (const float*)d_in[5];
    const float* bq = (const float*)d_in[6];
    const float* Wk = (const float*)d_in[7];
    const float* bk = (const float*)d_in[8];
    const float* Wv = (const float*)d_in[9];
    const float* bv = (const float*)d_in[10];
    const float* Wo = (const float*)d_in[11];
    const float* bo = (const float*)d_in[12];

    cudaFuncSetAttribute(attn_tc_kernel,
                         cudaFuncAttributeMaxDynamicSharedMemorySize,
                         ATTN_SMEM_BYTES);
    cudaFuncSetAttribute(gemm_qkv_tc,
                         cudaFuncAttributeMaxDynamicSharedMemorySize,
                         GEMM_SMEM_BYTES);
    cudaFuncSetAttribute(gemm_o_tc,
                         cudaFuncAttributeMaxDynamicSharedMemorySize,
                         GEMM_SMEM_BYTES);

    prep_kernel<<<96, 256>>>(x, Wq, Wk, Wv, Wo, mask);

    gemm_qkv_tc<<<dim3(32, 4, 3), 256, GEMM_SMEM_BYTES>>>(bq, bk, bv);

    attn_tc_kernel<<<dim3(16, 32), 128, ATTN_SMEM_BYTES>>>(edge, spat, rnk);

    gemm_o_tc<<<dim3(32, 4), 256, GEMM_SMEM_BYTES>>>(bo, (float*)d_out);
}

// round 14
// speedup vs baseline: 1.1007x; 1.1007x over previous
#include <cuda_runtime.h>
#include <math.h>

#define BATCH   4
#define N_SEQ   1024
#define D_MODEL 256
#define N_HEADS 8
#define D_HEAD  32
#define ATT_SCALE 0.17677669529663687f   // 1/sqrt(32)

// Scratch (device globals: no allocation allowed in kernel_launch)
__device__ float g_Q[BATCH * N_HEADS * N_SEQ * D_HEAD];   // [b,h,n,dk]  tf32, pre-scaled
__device__ float g_K[BATCH * N_HEADS * N_SEQ * D_HEAD];   // tf32-rounded
__device__ float g_V[BATCH * N_HEADS * N_SEQ * D_HEAD];   // tf32-rounded
__device__ float g_AO[BATCH * N_SEQ * D_MODEL];           // attention out, tf32-rounded
__device__ float g_maskval[BATCH * N_SEQ];                // 0 or -inf per key

__device__ __forceinline__ unsigned f2tf32(float f) {
    unsigned u;
    asm("cvt.rna.tf32.f32 %0, %1;" : "=r"(u) : "f"(f));
    return u;
}

#define MMA_TF32(d, a, b)                                                     \
    asm volatile(                                                             \
        "mma.sync.aligned.m16n8k8.row.col.f32.tf32.tf32.f32 "                 \
        "{%0,%1,%2,%3}, {%4,%5,%6,%7}, {%8,%9}, {%0,%1,%2,%3};\n"             \
        : "+f"((d)[0]), "+f"((d)[1]), "+f"((d)[2]), "+f"((d)[3])              \
        : "r"((a)[0]), "r"((a)[1]), "r"((a)[2]), "r"((a)[3]),                 \
          "r"((b)[0]), "r"((b)[1]))

__device__ __forceinline__ void cp_async16(void* s, const void* g) {
    unsigned sa = (unsigned)__cvta_generic_to_shared(s);
    asm volatile("cp.async.cg.shared.global [%0], [%1], 16;" :: "r"(sa), "l"(g));
}
#define CP_COMMIT() asm volatile("cp.async.commit_group;")
#define CP_WAIT0()  asm volatile("cp.async.wait_group 0;")
#define CP_WAIT1()  asm volatile("cp.async.wait_group 1;")

// ---------------------------------------------------------------------------
// QKV projection (round-9: split-z, 128x64 tile, mask folded). grid=(32,4,3),
// block=256.
// ---------------------------------------------------------------------------
#define GEMM_SMEM_BYTES (13824 * 4)

__global__ __launch_bounds__(256) void gemm_qkv_tc(
    const float* __restrict__ x,
    const float* __restrict__ Wq, const float* __restrict__ Wk, const float* __restrict__ Wv,
    const float* __restrict__ bq, const float* __restrict__ bk, const float* __restrict__ bv,
    const void* __restrict__ mraw)
{
    extern __shared__ float sm[];
    float* As = sm;            // [2][128][36]
    float* Ws = sm + 9216;     // [2][64][36]

    if (blockIdx.x == 0 && blockIdx.y == 0 && blockIdx.z == 0) {
        const int tid = threadIdx.x;
        const unsigned* mi = (const unsigned*)mraw;
        int ok_int = 1, ok_float = 1;
        for (int i = tid; i < 1024; i += 256) {
            unsigned v = mi[i];
            if (v > 1u) ok_int = 0;
            if (v != 0u && v != 0x3F800000u) ok_float = 0;
        }
        int all_int   = __syncthreads_and(ok_int);
        int all_float = __syncthreads_and(ok_float);
        const int mode = all_int ? 0 : (all_float ? 1 : 2);
        const float NEG_INF = __int_as_float(0xff800000);
        for (int i = tid; i < BATCH * N_SEQ; i += 256) {
            int masked;
            if (mode == 0)      masked = ((const int*)mraw)[i] != 0;
            else if (mode == 1) masked = ((const unsigned*)mraw)[i] != 0u;
            else                masked = ((const unsigned char*)mraw)[i] != 0;
            g_maskval[i] = masked ? NEG_INF : 0.0f;
        }
    }

    const int z = blockIdx.z;
    const float* W    = (z == 0) ? Wq : (z == 1) ? Wk : Wv;
    const float* bias = (z == 0) ? bq : (z == 1) ? bk : bv;
    float* out        = (z == 0) ? g_Q : (z == 1) ? g_K : g_V;

    const int tid  = threadIdx.x;
    const int lane = tid & 31;
    const int w    = tid >> 5;
    const int g    = lane >> 2;
    const int t    = lane & 3;
    const int w16  = w * 16;
    const int rbase = blockIdx.x * 128;
    const int cbase = blockIdx.y * 64;

    float sc[8][4];
#pragma unroll
    for (int n = 0; n < 8; n++)
#pragma unroll
        for (int j = 0; j < 4; j++) sc[n][j] = 0.0f;

    auto prefetch = [&](int c) {
        const int k0 = c * 32, st = c & 1;
        float* Ap = As + st * 4608;
        float* Wp = Ws + st * 2304;
#pragma unroll
        for (int it = 0; it < 4; it++) {
            int s = it * 256 + tid;
            int row = s >> 3;
            int c4 = (s & 7) * 4;
            cp_async16(&Ap[row * 36 + c4], &x[(size_t)(rbase + row) * D_MODEL + k0 + c4]);
        }
#pragma unroll
        for (int it = 0; it < 2; it++) {
            int s = it * 256 + tid;
            int row = s >> 3;
            int c4 = (s & 7) * 4;
            cp_async16(&Wp[row * 36 + c4], &W[(size_t)(cbase + row) * D_MODEL + k0 + c4]);
        }
        CP_COMMIT();
    };

    prefetch(0);
    for (int c = 0; c < 8; c++) {
        const int st = c & 1;
        const float* Ap = As + st * 4608;
        const float* Wp = Ws + st * 2304;
        if (c < 7) { prefetch(c + 1); CP_WAIT1(); }
        else       { CP_WAIT0(); }
        __syncthreads();

        unsigned qa[4][4];
#pragma unroll
        for (int kk = 0; kk < 4; kk++) {
            qa[kk][0] = f2tf32(Ap[(w16 + g    ) * 36 + kk * 8 + t    ]);
            qa[kk][1] = f2tf32(Ap[(w16 + g + 8) * 36 + kk * 8 + t    ]);
            qa[kk][2] = f2tf32(Ap[(w16 + g    ) * 36 + kk * 8 + t + 4]);
            qa[kk][3] = f2tf32(Ap[(w16 + g + 8) * 36 + kk * 8 + t + 4]);
        }
#pragma unroll
        for (int n8 = 0; n8 < 8; n8++) {
#pragma unroll
            for (int kk = 0; kk < 4; kk++) {
                unsigned bb[2];
                bb[0] = f2tf32(Wp[(n8 * 8 + g) * 36 + kk * 8 + t    ]);
                bb[1] = f2tf32(Wp[(n8 * 8 + g) * 36 + kk * 8 + t + 4]);
                MMA_TF32(sc[n8], qa[kk], bb);
            }
        }
        __syncthreads();
    }

    const float scale = (z == 0) ? ATT_SCALE : 1.0f;
#pragma unroll
    for (int n8 = 0; n8 < 8; n8++) {
        int c0 = cbase + n8 * 8 + 2 * t;
        float b0v = bias[c0], b1v = bias[c0 + 1];
        int r0 = rbase + w16 + g;
        int r1 = r0 + 8;
        float2 v0, v1;
        v0.x = __uint_as_float(f2tf32((sc[n8][0] + b0v) * scale));
        v0.y = __uint_as_float(f2tf32((sc[n8][1] + b1v) * scale));
        v1.x = __uint_as_float(f2tf32((sc[n8][2] + b0v) * scale));
        v1.y = __uint_as_float(f2tf32((sc[n8][3] + b1v) * scale));
        int h = c0 >> 5, dk = c0 & 31;
        int b0i = r0 >> 10, n0 = r0 & 1023;
        int b1i = r1 >> 10, n1 = r1 & 1023;
        *(float2*)&out[(size_t)(((b0i << 3) + h) * N_SEQ + n0) * D_HEAD + dk] = v0;
        *(float2*)&out[(size_t)(((b1i << 3) + h) * N_SEQ + n1) * D_HEAD + dk] = v1;
    }
}

// ---------------------------------------------------------------------------
// Output projection (round-9). grid=(32,4), block=256.
// ---------------------------------------------------------------------------
__global__ __launch_bounds__(256) void gemm_o_tc(
    const float* __restrict__ W, const float* __restrict__ bias,
    float* __restrict__ out)
{
    extern __shared__ float sm[];
    float* As = sm;
    float* Ws = sm + 9216;

    const int tid  = threadIdx.x;
    const int lane = tid & 31;
    const int w    = tid >> 5;
    const int g    = lane >> 2;
    const int t    = lane & 3;
    const int w16  = w * 16;
    const int rbase = blockIdx.x * 128;
    const int cbase = blockIdx.y * 64;

    float sc[8][4];
#pragma unroll
    for (int n = 0; n < 8; n++)
#pragma unroll
        for (int j = 0; j < 4; j++) sc[n][j] = 0.0f;

    auto prefetch = [&](int c) {
        const int k0 = c * 32, st = c & 1;
        float* Ap = As + st * 4608;
        float* Wp = Ws + st * 2304;
#pragma unroll
        for (int it = 0; it < 4; it++) {
            int s = it * 256 + tid;
            int row = s >> 3;
            int c4 = (s & 7) * 4;
            cp_async16(&Ap[row * 36 + c4], &g_AO[(size_t)(rbase + row) * D_MODEL + k0 + c4]);
        }
#pragma unroll
        for (int it = 0; it < 2; it++) {
            int s = it * 256 + tid;
            int row = s >> 3;
            int c4 = (s & 7) * 4;
            cp_async16(&Wp[row * 36 + c4], &W[(size_t)(cbase + row) * D_MODEL + k0 + c4]);
        }
        CP_COMMIT();
    };

    prefetch(0);
    for (int c = 0; c < 8; c++) {
        const int st = c & 1;
        const float* Ap = As + st * 4608;
        const float* Wp = Ws + st * 2304;
        if (c < 7) { prefetch(c + 1); CP_WAIT1(); }
        else       { CP_WAIT0(); }
        __syncthreads();

        unsigned qa[4][4];
#pragma unroll
        for (int kk = 0; kk < 4; kk++) {
            qa[kk][0] = __float_as_uint(Ap[(w16 + g    ) * 36 + kk * 8 + t    ]);
            qa[kk][1] = __float_as_uint(Ap[(w16 + g + 8) * 36 + kk * 8 + t    ]);
            qa[kk][2] = __float_as_uint(Ap[(w16 + g    ) * 36 + kk * 8 + t + 4]);
            qa[kk][3] = __float_as_uint(Ap[(w16 + g + 8) * 36 + kk * 8 + t + 4]);
        }
#pragma unroll
        for (int n8 = 0; n8 < 8; n8++) {
#pragma unroll
            for (int kk = 0; kk < 4; kk++) {
                unsigned bb[2];
                bb[0] = f2tf32(Wp[(n8 * 8 + g) * 36 + kk * 8 + t    ]);
                bb[1] = f2tf32(Wp[(n8 * 8 + g) * 36 + kk * 8 + t + 4]);
                MMA_TF32(sc[n8], qa[kk], bb);
            }
        }
        __syncthreads();
    }

#pragma unroll
    for (int n8 = 0; n8 < 8; n8++) {
        int c0 = cbase + n8 * 8 + 2 * t;
        float b0v = bias[c0], b1v = bias[c0 + 1];
        int r0 = rbase + w16 + g;
        int r1 = r0 + 8;
        float2 v0, v1;
        v0.x = sc[n8][0] + b0v;  v0.y = sc[n8][1] + b1v;
        v1.x = sc[n8][2] + b0v;  v1.y = sc[n8][3] + b1v;
        *(float2*)&out[(size_t)r0 * D_MODEL + c0] = v0;
        *(float2*)&out[(size_t)r1 * D_MODEL + c0] = v1;
    }
}

// ---------------------------------------------------------------------------
// Tensor-core flash attention — round-9 base with SPLIT commit groups:
// KV(i) and BIAS(i) are separate groups. Tile schedule:
//   wait_group 1 (KV(i) done, BIAS(i) may pend) -> sync -> S-mma
//   wait_group 0 (BIAS(i) done) -> sync -> issue KV(i+1)
//   bias-combine -> softmax -> sync -> issue BIAS(i+1) -> syncwarp -> PV
// S-mma now covers the bias stream's tail latency.
// grid=(16,32), block=128, 108.5 KB smem -> 2 CTAs/SM.
// ---------------------------------------------------------------------------
#define ATTN_SMEM_BYTES (27136 * 4)

__global__ __launch_bounds__(128) void attn_tc_kernel(
    const float* __restrict__ edge,
    const float* __restrict__ spat,
    const float* __restrict__ rnk)
{
    extern __shared__ float dsm[];
    float* KsB = dsm;                 // 2 * 64*36
    float* VsB = dsm + 4608;          // 2 * 64*40
    float* Ps  = dsm + 9728;          // 64*68
    float* BE  = dsm + 14080;         // 64*68
    float* BS  = BE + 4352;
    float* BR  = BS + 4352;

    const int tid  = threadIdx.x;
    const int lane = tid & 31;
    const int w    = tid >> 5;
    const int g    = lane >> 2;
    const int t    = lane & 3;
    const int qb   = blockIdx.x * 64;
    const int bh   = blockIdx.y;
    const int b    = bh >> 3;
    const int h    = bh & 7;
    const int w16  = w * 16;

    const float* Kg0 = g_K + (size_t)bh * N_SEQ * D_HEAD;
    const float* Vg0 = g_V + (size_t)bh * N_SEQ * D_HEAD;
    const float* maskp = g_maskval + b * N_SEQ;
    const float* eg0 = edge + ((size_t)bh * N_SEQ + qb) * N_SEQ;
    const float* sg0 = spat + ((size_t)bh * N_SEQ + qb) * N_SEQ;
    const float* rg0 = rnk  + ((size_t)bh * N_SEQ + qb) * N_SEQ;

    // issue K/V for tile i into slot i&1 (own commit group)
    auto issue_kv = [&](int i) {
        const int kb = i * 64;
        const int slot = i & 1;
        const float* Kg = Kg0 + (size_t)kb * D_HEAD;
        const float* Vg = Vg0 + (size_t)kb * D_HEAD;
        float* Ka = KsB + slot * 2304;
        float* Va = VsB + slot * 2560;
#pragma unroll
        for (int it = 0; it < 4; it++) {
            int s = it * 128 + tid;
            int row = s >> 3;
            int c4 = (s & 7) * 4;
            cp_async16(&Ka[row * 36 + c4], &Kg[row * D_HEAD + c4]);
            cp_async16(&Va[row * 40 + c4], &Vg[row * D_HEAD + c4]);
        }
        CP_COMMIT();
    };
    // issue biases for tile i into the single stage (own commit group)
    auto issue_bias = [&](int i) {
        const int kb = i * 64;
        const float* eg = eg0 + kb;
        const float* sg = sg0 + kb;
        const float* rg = rg0 + kb;
#pragma unroll
        for (int it = 0; it < 8; it++) {
            int s = it * 128 + tid;
            int row = s >> 4;
            int c4 = (s & 15) * 4;
            size_t go = (size_t)row * N_SEQ + c4;
            int so = row * 68 + c4;
            cp_async16(&BE[so], &eg[go]);
            cp_async16(&BS[so], &sg[go]);
            cp_async16(&BR[so], &rg[go]);
        }
        CP_COMMIT();
    };

    // ---- Prologue: KV(0), BIAS(0), Q; drain all (one-time) ----
    issue_kv(0);
    issue_bias(0);
    const float* Qg = g_Q + ((size_t)bh * N_SEQ + qb) * D_HEAD;
#pragma unroll
    for (int it = 0; it < 4; it++) {
        int s = it * 128 + tid;
        int row = s >> 3;
        int c4 = (s & 7) * 4;
        cp_async16(&Ps[row * 68 + c4], &Qg[row * D_HEAD + c4]);
    }
    CP_COMMIT();
    CP_WAIT0();
    __syncthreads();

    unsigned qa[4][4];
#pragma unroll
    for (int kk = 0; kk < 4; kk++) {
        qa[kk][0] = __float_as_uint(Ps[(w16 + g    ) * 68 + kk * 8 + t    ]);
        qa[kk][1] = __float_as_uint(Ps[(w16 + g + 8) * 68 + kk * 8 + t    ]);
        qa[kk][2] = __float_as_uint(Ps[(w16 + g    ) * 68 + kk * 8 + t + 4]);
        qa[kk][3] = __float_as_uint(Ps[(w16 + g + 8) * 68 + kk * 8 + t + 4]);
    }
    __syncthreads();   // all warps hold Q frags before Ps is reused for P

    float2 mkc[8];
#pragma unroll
    for (int n8 = 0; n8 < 8; n8++)
        mkc[n8] = *(const float2*)&maskp[n8 * 8 + 2 * t];

    float o[4][4];
#pragma unroll
    for (int n = 0; n < 4; n++)
#pragma unroll
        for (int j = 0; j < 4; j++) o[n][j] = 0.0f;

    float m0 = __int_as_float(0xff800000), m1 = m0;
    float l0 = 0.0f, l1 = 0.0f;

    for (int i = 0; i < 16; i++) {
        const int kb = i * 64;
        const int cur = i & 1;
        float* Ks = KsB + cur * 2304;
        float* Vs = VsB + cur * 2560;

        // 1. KV(i) complete (BIAS(i) may still be in flight); all warps done
        //    with tile i-1 (PV read Vs(alt) before this barrier).
        CP_WAIT1();
        __syncthreads();

        // 2. S = Q K^T — covers BIAS(i) tail latency
        float sc[8][4];
#pragma unroll
        for (int n8 = 0; n8 < 8; n8++) {
            sc[n8][0] = sc[n8][1] = sc[n8][2] = sc[n8][3] = 0.0f;
#pragma unroll
            for (int kk = 0; kk < 4; kk++) {
                unsigned bb[2];
                bb[0] = __float_as_uint(Ks[(n8 * 8 + g) * 36 + kk * 8 + t    ]);
                bb[1] = __float_as_uint(Ks[(n8 * 8 + g) * 36 + kk * 8 + t + 4]);
                MMA_TF32(sc[n8], qa[kk], bb);
            }
        }

        // 3. BIAS(i) complete + visible to all threads
        CP_WAIT0();
        __syncthreads();

        // 4. issue KV(i+1) now (slot alt free; overlaps rest of tile)
        if (i < 15) issue_kv(i + 1);

        // 5. combine biases + mask
#pragma unroll
        for (int n8 = 0; n8 < 8; n8++) {
            int c0 = n8 * 8 + 2 * t;
            int ro0 = (w16 + g    ) * 68 + c0;
            int ro1 = (w16 + g + 8) * 68 + c0;
            float2 e0 = *(float2*)&BE[ro0], e1 = *(float2*)&BE[ro1];
            float2 s0 = *(float2*)&BS[ro0], s1 = *(float2*)&BS[ro1];
            float2 r0 = *(float2*)&BR[ro0], r1 = *(float2*)&BR[ro1];
            float2 mk = mkc[n8];
            sc[n8][0] += (e0.x + s0.x) + (r0.x + mk.x);
            sc[n8][1] += (e0.y + s0.y) + (r0.y + mk.y);
            sc[n8][2] += (e1.x + s1.x) + (r1.x + mk.x);
            sc[n8][3] += (e1.y + s1.y) + (r1.y + mk.y);
        }

        // 6. online softmax
        float ml0 = sc[0][0], ml1 = sc[0][2];
#pragma unroll
        for (int n8 = 0; n8 < 8; n8++) {
            ml0 = fmaxf(ml0, fmaxf(sc[n8][0], sc[n8][1]));
            ml1 = fmaxf(ml1, fmaxf(sc[n8][2], sc[n8][3]));
        }
        ml0 = fmaxf(ml0, __shfl_xor_sync(0xffffffffu, ml0, 1));
        ml0 = fmaxf(ml0, __shfl_xor_sync(0xffffffffu, ml0, 2));
        ml1 = fmaxf(ml1, __shfl_xor_sync(0xffffffffu, ml1, 1));
        ml1 = fmaxf(ml1, __shfl_xor_sync(0xffffffffu, ml1, 2));

        float mn0 = fmaxf(m0, ml0);
        float mn1 = fmaxf(m1, ml1);
        float mc0 = fmaxf(mn0, -1e30f);
        float mc1 = fmaxf(mn1, -1e30f);
        float rs0 = __expf(fmaxf(m0, -1e30f) - mc0);
        float rs1 = __expf(fmaxf(m1, -1e30f) - mc1);
        m0 = mn0; m1 = mn1;

        float sum0 = 0.0f, sum1 = 0.0f;
#pragma unroll
        for (int n8 = 0; n8 < 8; n8++) {
            float p0 = __expf(sc[n8][0] - mc0);
            float p1 = __expf(sc[n8][1] - mc0);
            float p2 = __expf(sc[n8][2] - mc1);
            float p3 = __expf(sc[n8][3] - mc1);
            sum0 += p0 + p1;
            sum1 += p2 + p3;
            float2 w0, w1;
            w0.x = __uint_as_float(f2tf32(p0)); w0.y = __uint_as_float(f2tf32(p1));
            w1.x = __uint_as_float(f2tf32(p2)); w1.y = __uint_as_float(f2tf32(p3));
            *(float2*)&Ps[(w16 + g    ) * 68 + n8 * 8 + 2 * t] = w0;
            *(float2*)&Ps[(w16 + g + 8) * 68 + n8 * 8 + 2 * t] = w1;
        }
        sum0 += __shfl_xor_sync(0xffffffffu, sum0, 1);
        sum0 += __shfl_xor_sync(0xffffffffu, sum0, 2);
        sum1 += __shfl_xor_sync(0xffffffffu, sum1, 1);
        sum1 += __shfl_xor_sync(0xffffffffu, sum1, 2);
        l0 = l0 * rs0 + sum0;
        l1 = l1 * rs1 + sum1;

#pragma unroll
        for (int n = 0; n < 4; n++) {
            o[n][0] *= rs0; o[n][1] *= rs0;
            o[n][2] *= rs1; o[n][3] *= rs1;
        }

        // 7. all warps done reading bias stage -> refill it for tile i+1
        __syncthreads();
        if (i < 15) {
            issue_bias(i + 1);
#pragma unroll
            for (int n8 = 0; n8 < 8; n8++)
                mkc[n8] = *(const float2*)&maskp[kb + 64 + n8 * 8 + 2 * t];
        }

        __syncwarp();   // this warp's Ps rows visible warp-wide

        // 8. O += P V
#pragma unroll
        for (int kk = 0; kk < 8; kk++) {
            unsigned pa[4];
            pa[0] = __float_as_uint(Ps[(w16 + g    ) * 68 + kk * 8 + t    ]);
            pa[1] = __float_as_uint(Ps[(w16 + g + 8) * 68 + kk * 8 + t    ]);
            pa[2] = __float_as_uint(Ps[(w16 + g    ) * 68 + kk * 8 + t + 4]);
            pa[3] = __float_as_uint(Ps[(w16 + g + 8) * 68 + kk * 8 + t + 4]);
#pragma unroll
            for (int n = 0; n < 4; n++) {
                unsigned bb[2];
                bb[0] = __float_as_uint(Vs[(kk * 8 + t    ) * 40 + n * 8 + g]);
                bb[1] = __float_as_uint(Vs[(kk * 8 + t + 4) * 40 + n * 8 + g]);
                MMA_TF32(o[n], pa, bb);
            }
        }
    }

    // normalize + scatter (tf32-rounded for the O-projection mma)
    float inv0 = (l0 > 0.0f) ? (1.0f / l0) : 0.0f;
    float inv1 = (l1 > 0.0f) ? (1.0f / l1) : 0.0f;
    const int r0 = qb + w16 + g;
    const int r1 = r0 + 8;
#pragma unroll
    for (int n = 0; n < 4; n++) {
        int d = n * 8 + 2 * t;
        float2 v0, v1;
        v0.x = __uint_as_float(f2tf32(o[n][0] * inv0));
        v0.y = __uint_as_float(f2tf32(o[n][1] * inv0));
        v1.x = __uint_as_float(f2tf32(o[n][2] * inv1));
        v1.y = __uint_as_float(f2tf32(o[n][3] * inv1));
        *(float2*)&g_AO[((size_t)(b * N_SEQ + r0)) * D_MODEL + h * D_HEAD + d] = v0;
        *(float2*)&g_AO[((size_t)(b * N_SEQ + r1)) * D_MODEL + h * D_HEAD + d] = v1;
    }
}

// ---------------------------------------------------------------------------
extern "C" void kernel_launch(void* const* d_in, const int* in_sizes, int n_in,
                              void* d_out, int out_size)
{
    const float* x    = (const float*)d_in[0];
    const float* edge = (const float*)d_in[1];
    const float* spat = (const float*)d_in[2];
    const float* rnk  = (const float*)d_in[3];
    const void*  mask = d_in[4];
    const float* Wq = (const float*)d_in[5];
    const float* bq = (const float*)d_in[6];
    const float* Wk = (const float*)d_in[7];
    const float* bk = (const float*)d_in[8];
    const float* Wv = (const float*)d_in[9];
    const float* bv = (const float*)d_in[10];
    const float* Wo = (const float*)d_in[11];
    const float* bo = (const float*)d_in[12];

    cudaFuncSetAttribute(attn_tc_kernel,
                         cudaFuncAttributeMaxDynamicSharedMemorySize,
                         ATTN_SMEM_BYTES);
    cudaFuncSetAttribute(gemm_qkv_tc,
                         cudaFuncAttributeMaxDynamicSharedMemorySize,
                         GEMM_SMEM_BYTES);
    cudaFuncSetAttribute(gemm_o_tc,
                         cudaFuncAttributeMaxDynamicSharedMemorySize,
                         GEMM_SMEM_BYTES);

    gemm_qkv_tc<<<dim3(32, 4, 3), 256, GEMM_SMEM_BYTES>>>(
        x, Wq, Wk, Wv, bq, bk, bv, mask);

    attn_tc_kernel<<<dim3(16, 32), 128, ATTN_SMEM_BYTES>>>(edge, spat, rnk);

    gemm_o_tc<<<dim3(32, 4), 256, GEMM_SMEM_BYTES>>>(Wo, bo, (float*)d_out);
}

// round 15
// speedup vs baseline: 1.1019x; 1.0011x over previous
#include <cuda_runtime.h>
#include <math.h>

#define BATCH   4
#define N_SEQ   1024
#define D_MODEL 256
#define N_HEADS 8
#define D_HEAD  32
#define ATT_SCALE 0.17677669529663687f   // 1/sqrt(32)

// Scratch (device globals: no allocation allowed in kernel_launch)
__device__ float g_Q[BATCH * N_HEADS * N_SEQ * D_HEAD];   // [b,h,n,dk]  tf32, pre-scaled
__device__ float g_K[BATCH * N_HEADS * N_SEQ * D_HEAD];   // tf32-rounded
__device__ float g_V[BATCH * N_HEADS * N_SEQ * D_HEAD];   // tf32-rounded
__device__ float g_AO[BATCH * N_SEQ * D_MODEL];           // attention out, tf32-rounded
__device__ float g_maskval[BATCH * N_SEQ];                // 0 or -inf per key

__device__ __forceinline__ unsigned f2tf32(float f) {
    unsigned u;
    asm("cvt.rna.tf32.f32 %0, %1;" : "=r"(u) : "f"(f));
    return u;
}

#define MMA_TF32(d, a, b)                                                     \
    asm volatile(                                                             \
        "mma.sync.aligned.m16n8k8.row.col.f32.tf32.tf32.f32 "                 \
        "{%0,%1,%2,%3}, {%4,%5,%6,%7}, {%8,%9}, {%0,%1,%2,%3};\n"             \
        : "+f"((d)[0]), "+f"((d)[1]), "+f"((d)[2]), "+f"((d)[3])              \
        : "r"((a)[0]), "r"((a)[1]), "r"((a)[2]), "r"((a)[3]),                 \
          "r"((b)[0]), "r"((b)[1]))

__device__ __forceinline__ void cp_async16(void* s, const void* g) {
    unsigned sa = (unsigned)__cvta_generic_to_shared(s);
    asm volatile("cp.async.cg.shared.global [%0], [%1], 16;" :: "r"(sa), "l"(g));
}
#define CP_COMMIT() asm volatile("cp.async.commit_group;")
#define CP_WAIT0()  asm volatile("cp.async.wait_group 0;")
#define CP_WAIT1()  asm volatile("cp.async.wait_group 1;")

// ---------------------------------------------------------------------------
// QKV projection (round-9 structure; MMA loops interchanged kk-outer for
// accumulator ILP). grid=(32,4,3), block=256.
// ---------------------------------------------------------------------------
#define GEMM_SMEM_BYTES (13824 * 4)

__global__ __launch_bounds__(256) void gemm_qkv_tc(
    const float* __restrict__ x,
    const float* __restrict__ Wq, const float* __restrict__ Wk, const float* __restrict__ Wv,
    const float* __restrict__ bq, const float* __restrict__ bk, const float* __restrict__ bv,
    const void* __restrict__ mraw)
{
    extern __shared__ float sm[];
    float* As = sm;            // [2][128][36]
    float* Ws = sm + 9216;     // [2][64][36]

    if (blockIdx.x == 0 && blockIdx.y == 0 && blockIdx.z == 0) {
        const int tid = threadIdx.x;
        const unsigned* mi = (const unsigned*)mraw;
        int ok_int = 1, ok_float = 1;
        for (int i = tid; i < 1024; i += 256) {
            unsigned v = mi[i];
            if (v > 1u) ok_int = 0;
            if (v != 0u && v != 0x3F800000u) ok_float = 0;
        }
        int all_int   = __syncthreads_and(ok_int);
        int all_float = __syncthreads_and(ok_float);
        const int mode = all_int ? 0 : (all_float ? 1 : 2);
        const float NEG_INF = __int_as_float(0xff800000);
        for (int i = tid; i < BATCH * N_SEQ; i += 256) {
            int masked;
            if (mode == 0)      masked = ((const int*)mraw)[i] != 0;
            else if (mode == 1) masked = ((const unsigned*)mraw)[i] != 0u;
            else                masked = ((const unsigned char*)mraw)[i] != 0;
            g_maskval[i] = masked ? NEG_INF : 0.0f;
        }
    }

    const int z = blockIdx.z;
    const float* W    = (z == 0) ? Wq : (z == 1) ? Wk : Wv;
    const float* bias = (z == 0) ? bq : (z == 1) ? bk : bv;
    float* out        = (z == 0) ? g_Q : (z == 1) ? g_K : g_V;

    const int tid  = threadIdx.x;
    const int lane = tid & 31;
    const int w    = tid >> 5;
    const int g    = lane >> 2;
    const int t    = lane & 3;
    const int w16  = w * 16;
    const int rbase = blockIdx.x * 128;
    const int cbase = blockIdx.y * 64;

    float sc[8][4];
#pragma unroll
    for (int n = 0; n < 8; n++)
#pragma unroll
        for (int j = 0; j < 4; j++) sc[n][j] = 0.0f;

    auto prefetch = [&](int c) {
        const int k0 = c * 32, st = c & 1;
        float* Ap = As + st * 4608;
        float* Wp = Ws + st * 2304;
#pragma unroll
        for (int it = 0; it < 4; it++) {
            int s = it * 256 + tid;
            int row = s >> 3;
            int c4 = (s & 7) * 4;
            cp_async16(&Ap[row * 36 + c4], &x[(size_t)(rbase + row) * D_MODEL + k0 + c4]);
        }
#pragma unroll
        for (int it = 0; it < 2; it++) {
            int s = it * 256 + tid;
            int row = s >> 3;
            int c4 = (s & 7) * 4;
            cp_async16(&Wp[row * 36 + c4], &W[(size_t)(cbase + row) * D_MODEL + k0 + c4]);
        }
        CP_COMMIT();
    };

    prefetch(0);
    for (int c = 0; c < 8; c++) {
        const int st = c & 1;
        const float* Ap = As + st * 4608;
        const float* Wp = Ws + st * 2304;
        if (c < 7) { prefetch(c + 1); CP_WAIT1(); }
        else       { CP_WAIT0(); }
        __syncthreads();

        unsigned qa[4][4];
#pragma unroll
        for (int kk = 0; kk < 4; kk++) {
            qa[kk][0] = f2tf32(Ap[(w16 + g    ) * 36 + kk * 8 + t    ]);
            qa[kk][1] = f2tf32(Ap[(w16 + g + 8) * 36 + kk * 8 + t    ]);
            qa[kk][2] = f2tf32(Ap[(w16 + g    ) * 36 + kk * 8 + t + 4]);
            qa[kk][3] = f2tf32(Ap[(w16 + g + 8) * 36 + kk * 8 + t + 4]);
        }
        // kk OUTER, n8 INNER: consecutive MMAs hit different accumulators
#pragma unroll
        for (int kk = 0; kk < 4; kk++) {
#pragma unroll
            for (int n8 = 0; n8 < 8; n8++) {
                unsigned bb[2];
                bb[0] = f2tf32(Wp[(n8 * 8 + g) * 36 + kk * 8 + t    ]);
                bb[1] = f2tf32(Wp[(n8 * 8 + g) * 36 + kk * 8 + t + 4]);
                MMA_TF32(sc[n8], qa[kk], bb);
            }
        }
        __syncthreads();
    }

    const float scale = (z == 0) ? ATT_SCALE : 1.0f;
#pragma unroll
    for (int n8 = 0; n8 < 8; n8++) {
        int c0 = cbase + n8 * 8 + 2 * t;
        float b0v = bias[c0], b1v = bias[c0 + 1];
        int r0 = rbase + w16 + g;
        int r1 = r0 + 8;
        float2 v0, v1;
        v0.x = __uint_as_float(f2tf32((sc[n8][0] + b0v) * scale));
        v0.y = __uint_as_float(f2tf32((sc[n8][1] + b1v) * scale));
        v1.x = __uint_as_float(f2tf32((sc[n8][2] + b0v) * scale));
        v1.y = __uint_as_float(f2tf32((sc[n8][3] + b1v) * scale));
        int h = c0 >> 5, dk = c0 & 31;
        int b0i = r0 >> 10, n0 = r0 & 1023;
        int b1i = r1 >> 10, n1 = r1 & 1023;
        *(float2*)&out[(size_t)(((b0i << 3) + h) * N_SEQ + n0) * D_HEAD + dk] = v0;
        *(float2*)&out[(size_t)(((b1i << 3) + h) * N_SEQ + n1) * D_HEAD + dk] = v1;
    }
}

// ---------------------------------------------------------------------------
// Output projection (loops interchanged). grid=(32,4), block=256.
// ---------------------------------------------------------------------------
__global__ __launch_bounds__(256) void gemm_o_tc(
    const float* __restrict__ W, const float* __restrict__ bias,
    float* __restrict__ out)
{
    extern __shared__ float sm[];
    float* As = sm;
    float* Ws = sm + 9216;

    const int tid  = threadIdx.x;
    const int lane = tid & 31;
    const int w    = tid >> 5;
    const int g    = lane >> 2;
    const int t    = lane & 3;
    const int w16  = w * 16;
    const int rbase = blockIdx.x * 128;
    const int cbase = blockIdx.y * 64;

    float sc[8][4];
#pragma unroll
    for (int n = 0; n < 8; n++)
#pragma unroll
        for (int j = 0; j < 4; j++) sc[n][j] = 0.0f;

    auto prefetch = [&](int c) {
        const int k0 = c * 32, st = c & 1;
        float* Ap = As + st * 4608;
        float* Wp = Ws + st * 2304;
#pragma unroll
        for (int it = 0; it < 4; it++) {
            int s = it * 256 + tid;
            int row = s >> 3;
            int c4 = (s & 7) * 4;
            cp_async16(&Ap[row * 36 + c4], &g_AO[(size_t)(rbase + row) * D_MODEL + k0 + c4]);
        }
#pragma unroll
        for (int it = 0; it < 2; it++) {
            int s = it * 256 + tid;
            int row = s >> 3;
            int c4 = (s & 7) * 4;
            cp_async16(&Wp[row * 36 + c4], &W[(size_t)(cbase + row) * D_MODEL + k0 + c4]);
        }
        CP_COMMIT();
    };

    prefetch(0);
    for (int c = 0; c < 8; c++) {
        const int st = c & 1;
        const float* Ap = As + st * 4608;
        const float* Wp = Ws + st * 2304;
        if (c < 7) { prefetch(c + 1); CP_WAIT1(); }
        else       { CP_WAIT0(); }
        __syncthreads();

        unsigned qa[4][4];
#pragma unroll
        for (int kk = 0; kk < 4; kk++) {
            qa[kk][0] = __float_as_uint(Ap[(w16 + g    ) * 36 + kk * 8 + t    ]);
            qa[kk][1] = __float_as_uint(Ap[(w16 + g + 8) * 36 + kk * 8 + t    ]);
            qa[kk][2] = __float_as_uint(Ap[(w16 + g    ) * 36 + kk * 8 + t + 4]);
            qa[kk][3] = __float_as_uint(Ap[(w16 + g + 8) * 36 + kk * 8 + t + 4]);
        }
#pragma unroll
        for (int kk = 0; kk < 4; kk++) {
#pragma unroll
            for (int n8 = 0; n8 < 8; n8++) {
                unsigned bb[2];
                bb[0] = f2tf32(Wp[(n8 * 8 + g) * 36 + kk * 8 + t    ]);
                bb[1] = f2tf32(Wp[(n8 * 8 + g) * 36 + kk * 8 + t + 4]);
                MMA_TF32(sc[n8], qa[kk], bb);
            }
        }
        __syncthreads();
    }

#pragma unroll
    for (int n8 = 0; n8 < 8; n8++) {
        int c0 = cbase + n8 * 8 + 2 * t;
        float b0v = bias[c0], b1v = bias[c0 + 1];
        int r0 = rbase + w16 + g;
        int r1 = r0 + 8;
        float2 v0, v1;
        v0.x = sc[n8][0] + b0v;  v0.y = sc[n8][1] + b1v;
        v1.x = sc[n8][2] + b0v;  v1.y = sc[n8][3] + b1v;
        *(float2*)&out[(size_t)r0 * D_MODEL + c0] = v0;
        *(float2*)&out[(size_t)r1 * D_MODEL + c0] = v1;
    }
}

// ---------------------------------------------------------------------------
// Tensor-core flash attention — round-14 (split commit groups) with the
// S-mma loops interchanged (kk outer, n8 inner).
// grid=(16,32), block=128, 108.5 KB smem -> 2 CTAs/SM.
// ---------------------------------------------------------------------------
#define ATTN_SMEM_BYTES (27136 * 4)

__global__ __launch_bounds__(128) void attn_tc_kernel(
    const float* __restrict__ edge,
    const float* __restrict__ spat,
    const float* __restrict__ rnk)
{
    extern __shared__ float dsm[];
    float* KsB = dsm;                 // 2 * 64*36
    float* VsB = dsm + 4608;          // 2 * 64*40
    float* Ps  = dsm + 9728;          // 64*68
    float* BE  = dsm + 14080;         // 64*68
    float* BS  = BE + 4352;
    float* BR  = BS + 4352;

    const int tid  = threadIdx.x;
    const int lane = tid & 31;
    const int w    = tid >> 5;
    const int g    = lane >> 2;
    const int t    = lane & 3;
    const int qb   = blockIdx.x * 64;
    const int bh   = blockIdx.y;
    const int b    = bh >> 3;
    const int h    = bh & 7;
    const int w16  = w * 16;

    const float* Kg0 = g_K + (size_t)bh * N_SEQ * D_HEAD;
    const float* Vg0 = g_V + (size_t)bh * N_SEQ * D_HEAD;
    const float* maskp = g_maskval + b * N_SEQ;
    const float* eg0 = edge + ((size_t)bh * N_SEQ + qb) * N_SEQ;
    const float* sg0 = spat + ((size_t)bh * N_SEQ + qb) * N_SEQ;
    const float* rg0 = rnk  + ((size_t)bh * N_SEQ + qb) * N_SEQ;

    auto issue_kv = [&](int i) {
        const int kb = i * 64;
        const int slot = i & 1;
        const float* Kg = Kg0 + (size_t)kb * D_HEAD;
        const float* Vg = Vg0 + (size_t)kb * D_HEAD;
        float* Ka = KsB + slot * 2304;
        float* Va = VsB + slot * 2560;
#pragma unroll
        for (int it = 0; it < 4; it++) {
            int s = it * 128 + tid;
            int row = s >> 3;
            int c4 = (s & 7) * 4;
            cp_async16(&Ka[row * 36 + c4], &Kg[row * D_HEAD + c4]);
            cp_async16(&Va[row * 40 + c4], &Vg[row * D_HEAD + c4]);
        }
        CP_COMMIT();
    };
    auto issue_bias = [&](int i) {
        const int kb = i * 64;
        const float* eg = eg0 + kb;
        const float* sg = sg0 + kb;
        const float* rg = rg0 + kb;
#pragma unroll
        for (int it = 0; it < 8; it++) {
            int s = it * 128 + tid;
            int row = s >> 4;
            int c4 = (s & 15) * 4;
            size_t go = (size_t)row * N_SEQ + c4;
            int so = row * 68 + c4;
            cp_async16(&BE[so], &eg[go]);
            cp_async16(&BS[so], &sg[go]);
            cp_async16(&BR[so], &rg[go]);
        }
        CP_COMMIT();
    };

    // ---- Prologue ----
    issue_kv(0);
    issue_bias(0);
    const float* Qg = g_Q + ((size_t)bh * N_SEQ + qb) * D_HEAD;
#pragma unroll
    for (int it = 0; it < 4; it++) {
        int s = it * 128 + tid;
        int row = s >> 3;
        int c4 = (s & 7) * 4;
        cp_async16(&Ps[row * 68 + c4], &Qg[row * D_HEAD + c4]);
    }
    CP_COMMIT();
    CP_WAIT0();
    __syncthreads();

    unsigned qa[4][4];
#pragma unroll
    for (int kk = 0; kk < 4; kk++) {
        qa[kk][0] = __float_as_uint(Ps[(w16 + g    ) * 68 + kk * 8 + t    ]);
        qa[kk][1] = __float_as_uint(Ps[(w16 + g + 8) * 68 + kk * 8 + t    ]);
        qa[kk][2] = __float_as_uint(Ps[(w16 + g    ) * 68 + kk * 8 + t + 4]);
        qa[kk][3] = __float_as_uint(Ps[(w16 + g + 8) * 68 + kk * 8 + t + 4]);
    }
    __syncthreads();

    float2 mkc[8];
#pragma unroll
    for (int n8 = 0; n8 < 8; n8++)
        mkc[n8] = *(const float2*)&maskp[n8 * 8 + 2 * t];

    float o[4][4];
#pragma unroll
    for (int n = 0; n < 4; n++)
#pragma unroll
        for (int j = 0; j < 4; j++) o[n][j] = 0.0f;

    float m0 = __int_as_float(0xff800000), m1 = m0;
    float l0 = 0.0f, l1 = 0.0f;

    for (int i = 0; i < 16; i++) {
        const int kb = i * 64;
        const int cur = i & 1;
        float* Ks = KsB + cur * 2304;
        float* Vs = VsB + cur * 2560;

        // 1. KV(i) complete (BIAS(i) may still be in flight)
        CP_WAIT1();
        __syncthreads();

        // 2. S = Q K^T — kk outer, n8 inner (independent accumulators)
        float sc[8][4];
#pragma unroll
        for (int n8 = 0; n8 < 8; n8++) {
            sc[n8][0] = sc[n8][1] = sc[n8][2] = sc[n8][3] = 0.0f;
        }
#pragma unroll
        for (int kk = 0; kk < 4; kk++) {
#pragma unroll
            for (int n8 = 0; n8 < 8; n8++) {
                unsigned bb[2];
                bb[0] = __float_as_uint(Ks[(n8 * 8 + g) * 36 + kk * 8 + t    ]);
                bb[1] = __float_as_uint(Ks[(n8 * 8 + g) * 36 + kk * 8 + t + 4]);
                MMA_TF32(sc[n8], qa[kk], bb);
            }
        }

        // 3. BIAS(i) complete + visible
        CP_WAIT0();
        __syncthreads();

        // 4. issue KV(i+1)
        if (i < 15) issue_kv(i + 1);

        // 5. combine biases + mask
#pragma unroll
        for (int n8 = 0; n8 < 8; n8++) {
            int c0 = n8 * 8 + 2 * t;
            int ro0 = (w16 + g    ) * 68 + c0;
            int ro1 = (w16 + g + 8) * 68 + c0;
            float2 e0 = *(float2*)&BE[ro0], e1 = *(float2*)&BE[ro1];
            float2 s0 = *(float2*)&BS[ro0], s1 = *(float2*)&BS[ro1];
            float2 r0 = *(float2*)&BR[ro0], r1 = *(float2*)&BR[ro1];
            float2 mk = mkc[n8];
            sc[n8][0] += (e0.x + s0.x) + (r0.x + mk.x);
            sc[n8][1] += (e0.y + s0.y) + (r0.y + mk.y);
            sc[n8][2] += (e1.x + s1.x) + (r1.x + mk.x);
            sc[n8][3] += (e1.y + s1.y) + (r1.y + mk.y);
        }

        // 6. online softmax
        float ml0 = sc[0][0], ml1 = sc[0][2];
#pragma unroll
        for (int n8 = 0; n8 < 8; n8++) {
            ml0 = fmaxf(ml0, fmaxf(sc[n8][0], sc[n8][1]));
            ml1 = fmaxf(ml1, fmaxf(sc[n8][2], sc[n8][3]));
        }
        ml0 = fmaxf(ml0, __shfl_xor_sync(0xffffffffu, ml0, 1));
        ml0 = fmaxf(ml0, __shfl_xor_sync(0xffffffffu, ml0, 2));
        ml1 = fmaxf(ml1, __shfl_xor_sync(0xffffffffu, ml1, 1));
        ml1 = fmaxf(ml1, __shfl_xor_sync(0xffffffffu, ml1, 2));

        float mn0 = fmaxf(m0, ml0);
        float mn1 = fmaxf(m1, ml1);
        float mc0 = fmaxf(mn0, -1e30f);
        float mc1 = fmaxf(mn1, -1e30f);
        float rs0 = __expf(fmaxf(m0, -1e30f) - mc0);
        float rs1 = __expf(fmaxf(m1, -1e30f) - mc1);
        m0 = mn0; m1 = mn1;

        float sum0 = 0.0f, sum1 = 0.0f;
#pragma unroll
        for (int n8 = 0; n8 < 8; n8++) {
            float p0 = __expf(sc[n8][0] - mc0);
            float p1 = __expf(sc[n8][1] - mc0);
            float p2 = __expf(sc[n8][2] - mc1);
            float p3 = __expf(sc[n8][3] - mc1);
            sum0 += p0 + p1;
            sum1 += p2 + p3;
            float2 w0, w1;
            w0.x = __uint_as_float(f2tf32(p0)); w0.y = __uint_as_float(f2tf32(p1));
            w1.x = __uint_as_float(f2tf32(p2)); w1.y = __uint_as_float(f2tf32(p3));
            *(float2*)&Ps[(w16 + g    ) * 68 + n8 * 8 + 2 * t] = w0;
            *(float2*)&Ps[(w16 + g + 8) * 68 + n8 * 8 + 2 * t] = w1;
        }
        sum0 += __shfl_xor_sync(0xffffffffu, sum0, 1);
        sum0 += __shfl_xor_sync(0xffffffffu, sum0, 2);
        sum1 += __shfl_xor_sync(0xffffffffu, sum1, 1);
        sum1 += __shfl_xor_sync(0xffffffffu, sum1, 2);
        l0 = l0 * rs0 + sum0;
        l1 = l1 * rs1 + sum1;

#pragma unroll
        for (int n = 0; n < 4; n++) {
            o[n][0] *= rs0; o[n][1] *= rs0;
            o[n][2] *= rs1; o[n][3] *= rs1;
        }

        // 7. all warps done reading bias stage -> refill for tile i+1
        __syncthreads();
        if (i < 15) {
            issue_bias(i + 1);
#pragma unroll
            for (int n8 = 0; n8 < 8; n8++)
                mkc[n8] = *(const float2*)&maskp[kb + 64 + n8 * 8 + 2 * t];
        }

        __syncwarp();

        // 8. O += P V
#pragma unroll
        for (int kk = 0; kk < 8; kk++) {
            unsigned pa[4];
            pa[0] = __float_as_uint(Ps[(w16 + g    ) * 68 + kk * 8 + t    ]);
            pa[1] = __float_as_uint(Ps[(w16 + g + 8) * 68 + kk * 8 + t    ]);
            pa[2] = __float_as_uint(Ps[(w16 + g    ) * 68 + kk * 8 + t + 4]);
            pa[3] = __float_as_uint(Ps[(w16 + g + 8) * 68 + kk * 8 + t + 4]);
#pragma unroll
            for (int n = 0; n < 4; n++) {
                unsigned bb[2];
                bb[0] = __float_as_uint(Vs[(kk * 8 + t    ) * 40 + n * 8 + g]);
                bb[1] = __float_as_uint(Vs[(kk * 8 + t + 4) * 40 + n * 8 + g]);
                MMA_TF32(o[n], pa, bb);
            }
        }
    }

    // normalize + scatter (tf32-rounded for the O-projection mma)
    float inv0 = (l0 > 0.0f) ? (1.0f / l0) : 0.0f;
    float inv1 = (l1 > 0.0f) ? (1.0f / l1) : 0.0f;
    const int r0 = qb + w16 + g;
    const int r1 = r0 + 8;
#pragma unroll
    for (int n = 0; n < 4; n++) {
        int d = n * 8 + 2 * t;
        float2 v0, v1;
        v0.x = __uint_as_float(f2tf32(o[n][0] * inv0));
        v0.y = __uint_as_float(f2tf32(o[n][1] * inv0));
        v1.x = __uint_as_float(f2tf32(o[n][2] * inv1));
        v1.y = __uint_as_float(f2tf32(o[n][3] * inv1));
        *(float2*)&g_AO[((size_t)(b * N_SEQ + r0)) * D_MODEL + h * D_HEAD + d] = v0;
        *(float2*)&g_AO[((size_t)(b * N_SEQ + r1)) * D_MODEL + h * D_HEAD + d] = v1;
    }
}

// ---------------------------------------------------------------------------
extern "C" void kernel_launch(void* const* d_in, const int* in_sizes, int n_in,
                              void* d_out, int out_size)
{
    const float* x    = (const float*)d_in[0];
    const float* edge = (const float*)d_in[1];
    const float* spat = (const float*)d_in[2];
    const float* rnk  = (const float*)d_in[3];
    const void*  mask = d_in[4];
    const float* Wq = (const float*)d_in[5];
    const float* bq = (const float*)d_in[6];
    const float* Wk = (const float*)d_in[7];
    const float* bk = (const float*)d_in[8];
    const float* Wv = (const float*)d_in[9];
    const float* bv = (const float*)d_in[10];
    const float* Wo = (const float*)d_in[11];
    const float* bo = (const float*)d_in[12];

    cudaFuncSetAttribute(attn_tc_kernel,
                         cudaFuncAttributeMaxDynamicSharedMemorySize,
                         ATTN_SMEM_BYTES);
    cudaFuncSetAttribute(gemm_qkv_tc,
                         cudaFuncAttributeMaxDynamicSharedMemorySize,
                         GEMM_SMEM_BYTES);
    cudaFuncSetAttribute(gemm_o_tc,
                         cudaFuncAttributeMaxDynamicSharedMemorySize,
                         GEMM_SMEM_BYTES);

    gemm_qkv_tc<<<dim3(32, 4, 3), 256, GEMM_SMEM_BYTES>>>(
        x, Wq, Wk, Wv, bq, bk, bv, mask);

    attn_tc_kernel<<<dim3(16, 32), 128, ATTN_SMEM_BYTES>>>(edge, spat, rnk);

    gemm_o_tc<<<dim3(32, 4), 256, GEMM_SMEM_BYTES>>>(Wo, bo, (float*)d_out);
}

// round 16
// speedup vs baseline: 1.1329x; 1.0282x over previous
#include <cuda_runtime.h>
#include <cuda.h>
#include <math.h>

#define BATCH   4
#define N_SEQ   1024
#define D_MODEL 256
#define N_HEADS 8
#define D_HEAD  32
#define ATT_SCALE 0.17677669529663687f   // 1/sqrt(32)

// Scratch (device globals: no allocation allowed in kernel_launch)
__device__ float g_Q[BATCH * N_HEADS * N_SEQ * D_HEAD];   // [b,h,n,dk]  tf32, pre-scaled
__device__ float g_K[BATCH * N_HEADS * N_SEQ * D_HEAD];   // tf32-rounded
__device__ float g_V[BATCH * N_HEADS * N_SEQ * D_HEAD];   // tf32-rounded
__device__ float g_AO[BATCH * N_SEQ * D_MODEL];           // attention out, tf32-rounded
__device__ float g_maskval[BATCH * N_SEQ];                // 0 or -inf per key

__device__ __forceinline__ unsigned f2tf32(float f) {
    unsigned u;
    asm("cvt.rna.tf32.f32 %0, %1;" : "=r"(u) : "f"(f));
    return u;
}

#define MMA_TF32(d, a, b)                                                     \
    asm volatile(                                                             \
        "mma.sync.aligned.m16n8k8.row.col.f32.tf32.tf32.f32 "                 \
        "{%0,%1,%2,%3}, {%4,%5,%6,%7}, {%8,%9}, {%0,%1,%2,%3};\n"             \
        : "+f"((d)[0]), "+f"((d)[1]), "+f"((d)[2]), "+f"((d)[3])              \
        : "r"((a)[0]), "r"((a)[1]), "r"((a)[2]), "r"((a)[3]),                 \
          "r"((b)[0]), "r"((b)[1]))

__device__ __forceinline__ void cp_async16(void* s, const void* g) {
    unsigned sa = (unsigned)__cvta_generic_to_shared(s);
    asm volatile("cp.async.cg.shared.global [%0], [%1], 16;" :: "r"(sa), "l"(g));
}
#define CP_COMMIT() asm volatile("cp.async.commit_group;")
#define CP_WAIT0()  asm volatile("cp.async.wait_group 0;")
#define CP_WAIT1()  asm volatile("cp.async.wait_group 1;")

__device__ __forceinline__ void mbar_init(unsigned mbar, unsigned cnt) {
    asm volatile("mbarrier.init.shared.b64 [%0], %1;" :: "r"(mbar), "r"(cnt) : "memory");
}
__device__ __forceinline__ void mbar_expect_tx(unsigned mbar, unsigned bytes) {
    asm volatile("mbarrier.arrive.expect_tx.shared.b64 _, [%0], %1;"
                 :: "r"(mbar), "r"(bytes) : "memory");
}
__device__ __forceinline__ void mbar_wait(unsigned mbar, unsigned phase) {
    asm volatile(
        "{\n\t.reg .pred P1;\n\t"
        "WAIT_LOOP_%=:\n\t"
        "mbarrier.try_wait.parity.acquire.cta.shared::cta.b64 P1, [%0], %1, 0x989680;\n\t"
        "@P1 bra.uni WAIT_DONE_%=;\n\t"
        "bra.uni WAIT_LOOP_%=;\n\t"
        "WAIT_DONE_%=:\n\t}"
        :: "r"(mbar), "r"(phase) : "memory");
}
__device__ __forceinline__ void tma2d(unsigned dst, const CUtensorMap* m,
                                      int x, int y, unsigned mbar) {
    asm volatile(
        "cp.async.bulk.tensor.2d.shared::cta.global.tile.mbarrier::complete_tx::bytes "
        "[%0], [%1, {%2, %3}], [%4];"
        :: "r"(dst), "l"(m), "r"(x), "r"(y), "r"(mbar) : "memory");
}

// ---------------------------------------------------------------------------
// QKV projection (round-15). grid=(32,4,3), block=256, mask prep folded.
// ---------------------------------------------------------------------------
#define GEMM_SMEM_BYTES (13824 * 4)

__global__ __launch_bounds__(256) void gemm_qkv_tc(
    const float* __restrict__ x,
    const float* __restrict__ Wq, const float* __restrict__ Wk, const float* __restrict__ Wv,
    const float* __restrict__ bq, const float* __restrict__ bk, const float* __restrict__ bv,
    const void* __restrict__ mraw)
{
    extern __shared__ float sm[];
    float* As = sm;            // [2][128][36]
    float* Ws = sm + 9216;     // [2][64][36]

    if (blockIdx.x == 0 && blockIdx.y == 0 && blockIdx.z == 0) {
        const int tid = threadIdx.x;
        const unsigned* mi = (const unsigned*)mraw;
        int ok_int = 1, ok_float = 1;
        for (int i = tid; i < 1024; i += 256) {
            unsigned v = mi[i];
            if (v > 1u) ok_int = 0;
            if (v != 0u && v != 0x3F800000u) ok_float = 0;
        }
        int all_int   = __syncthreads_and(ok_int);
        int all_float = __syncthreads_and(ok_float);
        const int mode = all_int ? 0 : (all_float ? 1 : 2);
        const float NEG_INF = __int_as_float(0xff800000);
        for (int i = tid; i < BATCH * N_SEQ; i += 256) {
            int masked;
            if (mode == 0)      masked = ((const int*)mraw)[i] != 0;
            else if (mode == 1) masked = ((const unsigned*)mraw)[i] != 0u;
            else                masked = ((const unsigned char*)mraw)[i] != 0;
            g_maskval[i] = masked ? NEG_INF : 0.0f;
        }
    }

    const int z = blockIdx.z;
    const float* W    = (z == 0) ? Wq : (z == 1) ? Wk : Wv;
    const float* bias = (z == 0) ? bq : (z == 1) ? bk : bv;
    float* out        = (z == 0) ? g_Q : (z == 1) ? g_K : g_V;

    const int tid  = threadIdx.x;
    const int lane = tid & 31;
    const int w    = tid >> 5;
    const int g    = lane >> 2;
    const int t    = lane & 3;
    const int w16  = w * 16;
    const int rbase = blockIdx.x * 128;
    const int cbase = blockIdx.y * 64;

    float sc[8][4];
#pragma unroll
    for (int n = 0; n < 8; n++)
#pragma unroll
        for (int j = 0; j < 4; j++) sc[n][j] = 0.0f;

    auto prefetch = [&](int c) {
        const int k0 = c * 32, st = c & 1;
        float* Ap = As + st * 4608;
        float* Wp = Ws + st * 2304;
#pragma unroll
        for (int it = 0; it < 4; it++) {
            int s = it * 256 + tid;
            int row = s >> 3;
            int c4 = (s & 7) * 4;
            cp_async16(&Ap[row * 36 + c4], &x[(size_t)(rbase + row) * D_MODEL + k0 + c4]);
        }
#pragma unroll
        for (int it = 0; it < 2; it++) {
            int s = it * 256 + tid;
            int row = s >> 3;
            int c4 = (s & 7) * 4;
            cp_async16(&Wp[row * 36 + c4], &W[(size_t)(cbase + row) * D_MODEL + k0 + c4]);
        }
        CP_COMMIT();
    };

    prefetch(0);
    for (int c = 0; c < 8; c++) {
        const int st = c & 1;
        const float* Ap = As + st * 4608;
        const float* Wp = Ws + st * 2304;
        if (c < 7) { prefetch(c + 1); CP_WAIT1(); }
        else       { CP_WAIT0(); }
        __syncthreads();

        unsigned qa[4][4];
#pragma unroll
        for (int kk = 0; kk < 4; kk++) {
            qa[kk][0] = f2tf32(Ap[(w16 + g    ) * 36 + kk * 8 + t    ]);
            qa[kk][1] = f2tf32(Ap[(w16 + g + 8) * 36 + kk * 8 + t    ]);
            qa[kk][2] = f2tf32(Ap[(w16 + g    ) * 36 + kk * 8 + t + 4]);
            qa[kk][3] = f2tf32(Ap[(w16 + g + 8) * 36 + kk * 8 + t + 4]);
        }
#pragma unroll
        for (int kk = 0; kk < 4; kk++) {
#pragma unroll
            for (int n8 = 0; n8 < 8; n8++) {
                unsigned bb[2];
                bb[0] = f2tf32(Wp[(n8 * 8 + g) * 36 + kk * 8 + t    ]);
                bb[1] = f2tf32(Wp[(n8 * 8 + g) * 36 + kk * 8 + t + 4]);
                MMA_TF32(sc[n8], qa[kk], bb);
            }
        }
        __syncthreads();
    }

    const float scale = (z == 0) ? ATT_SCALE : 1.0f;
#pragma unroll
    for (int n8 = 0; n8 < 8; n8++) {
        int c0 = cbase + n8 * 8 + 2 * t;
        float b0v = bias[c0], b1v = bias[c0 + 1];
        int r0 = rbase + w16 + g;
        int r1 = r0 + 8;
        float2 v0, v1;
        v0.x = __uint_as_float(f2tf32((sc[n8][0] + b0v) * scale));
        v0.y = __uint_as_float(f2tf32((sc[n8][1] + b1v) * scale));
        v1.x = __uint_as_float(f2tf32((sc[n8][2] + b0v) * scale));
        v1.y = __uint_as_float(f2tf32((sc[n8][3] + b1v) * scale));
        int h = c0 >> 5, dk = c0 & 31;
        int b0i = r0 >> 10, n0 = r0 & 1023;
        int b1i = r1 >> 10, n1 = r1 & 1023;
        *(float2*)&out[(size_t)(((b0i << 3) + h) * N_SEQ + n0) * D_HEAD + dk] = v0;
        *(float2*)&out[(size_t)(((b1i << 3) + h) * N_SEQ + n1) * D_HEAD + dk] = v1;
    }
}

// ---------------------------------------------------------------------------
// Output projection (round-15). grid=(32,4), block=256.
// ---------------------------------------------------------------------------
__global__ __launch_bounds__(256) void gemm_o_tc(
    const float* __restrict__ W, const float* __restrict__ bias,
    float* __restrict__ out)
{
    extern __shared__ float sm[];
    float* As = sm;
    float* Ws = sm + 9216;

    const int tid  = threadIdx.x;
    const int lane = tid & 31;
    const int w    = tid >> 5;
    const int g    = lane >> 2;
    const int t    = lane & 3;
    const int w16  = w * 16;
    const int rbase = blockIdx.x * 128;
    const int cbase = blockIdx.y * 64;

    float sc[8][4];
#pragma unroll
    for (int n = 0; n < 8; n++)
#pragma unroll
        for (int j = 0; j < 4; j++) sc[n][j] = 0.0f;

    auto prefetch = [&](int c) {
        const int k0 = c * 32, st = c & 1;
        float* Ap = As + st * 4608;
        float* Wp = Ws + st * 2304;
#pragma unroll
        for (int it = 0; it < 4; it++) {
            int s = it * 256 + tid;
            int row = s >> 3;
            int c4 = (s & 7) * 4;
            cp_async16(&Ap[row * 36 + c4], &g_AO[(size_t)(rbase + row) * D_MODEL + k0 + c4]);
        }
#pragma unroll
        for (int it = 0; it < 2; it++) {
            int s = it * 256 + tid;
            int row = s >> 3;
            int c4 = (s & 7) * 4;
            cp_async16(&Wp[row * 36 + c4], &W[(size_t)(cbase + row) * D_MODEL + k0 + c4]);
        }
        CP_COMMIT();
    };

    prefetch(0);
    for (int c = 0; c < 8; c++) {
        const int st = c & 1;
        const float* Ap = As + st * 4608;
        const float* Wp = Ws + st * 2304;
        if (c < 7) { prefetch(c + 1); CP_WAIT1(); }
        else       { CP_WAIT0(); }
        __syncthreads();

        unsigned qa[4][4];
#pragma unroll
        for (int kk = 0; kk < 4; kk++) {
            qa[kk][0] = __float_as_uint(Ap[(w16 + g    ) * 36 + kk * 8 + t    ]);
            qa[kk][1] = __float_as_uint(Ap[(w16 + g + 8) * 36 + kk * 8 + t    ]);
            qa[kk][2] = __float_as_uint(Ap[(w16 + g    ) * 36 + kk * 8 + t + 4]);
            qa[kk][3] = __float_as_uint(Ap[(w16 + g + 8) * 36 + kk * 8 + t + 4]);
        }
#pragma unroll
        for (int kk = 0; kk < 4; kk++) {
#pragma unroll
            for (int n8 = 0; n8 < 8; n8++) {
                unsigned bb[2];
                bb[0] = f2tf32(Wp[(n8 * 8 + g) * 36 + kk * 8 + t    ]);
                bb[1] = f2tf32(Wp[(n8 * 8 + g) * 36 + kk * 8 + t + 4]);
                MMA_TF32(sc[n8], qa[kk], bb);
            }
        }
        __syncthreads();
    }

#pragma unroll
    for (int n8 = 0; n8 < 8; n8++) {
        int c0 = cbase + n8 * 8 + 2 * t;
        float b0v = bias[c0], b1v = bias[c0 + 1];
        int r0 = rbase + w16 + g;
        int r1 = r0 + 8;
        float2 v0, v1;
        v0.x = sc[n8][0] + b0v;  v0.y = sc[n8][1] + b1v;
        v1.x = sc[n8][2] + b0v;  v1.y = sc[n8][3] + b1v;
        *(float2*)&out[(size_t)r0 * D_MODEL + c0] = v0;
        *(float2*)&out[(size_t)r1 * D_MODEL + c0] = v1;
    }
}

// ---------------------------------------------------------------------------
// Tensor-core flash attention — TMA bias streaming at 2 CTAs/SM.
// grid=(16,32), block=128 (4 warps). k-tile = 32 keys, 32 iterations.
// Bias: 3 TMA 2D loads/tile (box 32x64, SW128) into a DOUBLE-buffered stage
// (mbarrier per slot, phase=(i>>1)&1), issued 2 tiles ahead.
// K/V: cp.async double-buffered, 2-tiles-ahead commit groups.
// Dynamic smem (floats):
//   Bias[2][3][2048] @ 0     (12288)   slot stride 6144; E/S/R at +0/+2048/+4096
//   KsB [2][32*36]   @ 12288 (2304)
//   VsB [2][32*40]   @ 14592 (2560)
//   Ps  [64*36]      @ 17152 (2304)   (Q staging in prologue; P thereafter)
//   mbar[2]          @ 19456 (4)
// total 19460 floats = 77840 B  -> 2 CTAs/SM.
// ---------------------------------------------------------------------------
#define ATTN_SMEM_BYTES (19460 * 4)

__global__ __launch_bounds__(128) void attn_tc_kernel(
    const __grid_constant__ CUtensorMap tmE,
    const __grid_constant__ CUtensorMap tmS,
    const __grid_constant__ CUtensorMap tmR)
{
    extern __shared__ float dsm[];
    float* KsB = dsm + 12288;
    float* VsB = dsm + 14592;
    float* Ps  = dsm + 17152;

    const unsigned smem_u32 = (unsigned)__cvta_generic_to_shared(dsm);
    const unsigned mbar_base = smem_u32 + 19456u * 4u;

    const int tid  = threadIdx.x;
    const int lane = tid & 31;
    const int w    = tid >> 5;
    const int g    = lane >> 2;
    const int t    = lane & 3;
    const int qb   = blockIdx.x * 64;
    const int bh   = blockIdx.y;
    const int b    = bh >> 3;
    const int h    = bh & 7;
    const int w16  = w * 16;

    const float* Kg0 = g_K + (size_t)bh * N_SEQ * D_HEAD;
    const float* Vg0 = g_V + (size_t)bh * N_SEQ * D_HEAD;
    const float* maskp = g_maskval + b * N_SEQ;
    const int yrow = bh * N_SEQ + qb;

    if (tid == 0) {
        mbar_init(mbar_base, 1);
        mbar_init(mbar_base + 8, 1);
    }
    __syncthreads();

    // TMA bias group for k-tile i into slot i&1 (24576 bytes expected)
    auto tma_bias = [&](int i) {
        if (tid == 0) {
            const int slot = i & 1;
            const unsigned mb = mbar_base + slot * 8;
            const unsigned sb = smem_u32 + (unsigned)(slot * 6144) * 4u;
            mbar_expect_tx(mb, 24576u);
            tma2d(sb,          &tmE, i * 32, yrow, mb);
            tma2d(sb + 8192u,  &tmS, i * 32, yrow, mb);
            tma2d(sb + 16384u, &tmR, i * 32, yrow, mb);
        }
    };
    // cp.async K/V for k-tile i into slot i&1 (own commit group)
    auto issue_kv = [&](int i) {
        const int kb = i * 32;
        const int slot = i & 1;
        const float* Kg = Kg0 + (size_t)kb * D_HEAD;
        const float* Vg = Vg0 + (size_t)kb * D_HEAD;
        float* Ka = KsB + slot * 1152;
        float* Va = VsB + slot * 1280;
#pragma unroll
        for (int it = 0; it < 2; it++) {
            int s = it * 128 + tid;     // 0..255
            int row = s >> 3;           // 0..31
            int c4 = (s & 7) * 4;
            cp_async16(&Ka[row * 36 + c4], &Kg[row * D_HEAD + c4]);
            cp_async16(&Va[row * 40 + c4], &Vg[row * D_HEAD + c4]);
        }
        CP_COMMIT();
    };

    // ---- Prologue: bias(0),(1) TMA; KV(0),(1); Q stage; drain cp.async ----
    tma_bias(0);
    tma_bias(1);
    issue_kv(0);
    issue_kv(1);
    const float* Qg = g_Q + ((size_t)bh * N_SEQ + qb) * D_HEAD;
#pragma unroll
    for (int it = 0; it < 4; it++) {
        int s = it * 128 + tid;         // 0..511
        int row = s >> 3;               // 0..63
        int c4 = (s & 7) * 4;
        cp_async16(&Ps[row * 36 + c4], &Qg[row * D_HEAD + c4]);
    }
    CP_COMMIT();
    CP_WAIT0();
    __syncthreads();

    unsigned qa[4][4];
#pragma unroll
    for (int kk = 0; kk < 4; kk++) {
        qa[kk][0] = __float_as_uint(Ps[(w16 + g    ) * 36 + kk * 8 + t    ]);
        qa[kk][1] = __float_as_uint(Ps[(w16 + g + 8) * 36 + kk * 8 + t    ]);
        qa[kk][2] = __float_as_uint(Ps[(w16 + g    ) * 36 + kk * 8 + t + 4]);
        qa[kk][3] = __float_as_uint(Ps[(w16 + g + 8) * 36 + kk * 8 + t + 4]);
    }
    __syncthreads();   // all warps hold Q frags before Ps reused for P

    float2 mkc[4];
#pragma unroll
    for (int n8 = 0; n8 < 4; n8++)
        mkc[n8] = *(const float2*)&maskp[n8 * 8 + 2 * t];

    float o[4][4];
#pragma unroll
    for (int n = 0; n < 4; n++)
#pragma unroll
        for (int j = 0; j < 4; j++) o[n][j] = 0.0f;

    float m0 = __int_as_float(0xff800000), m1 = m0;
    float l0 = 0.0f, l1 = 0.0f;

    const int r0i = w16 + g;           // q row (0..63) within this CTA's tile
    const int xr  = (r0i & 7) << 2;    // SW128 float-col XOR (same for r0i+8)

    for (int i = 0; i < 32; i++) {
        const int slot = i & 1;
        float* Ks = KsB + slot * 1152;
        float* Vs = VsB + slot * 1280;
        const float* BB = dsm + slot * 6144;

        // 1. KV(i) complete (KV(i+1) may stay in flight); bias(i) TMA done
        if (i == 31) { CP_WAIT0(); } else { CP_WAIT1(); }
        mbar_wait(mbar_base + slot * 8, (unsigned)((i >> 1) & 1));
        __syncthreads();

        // 2. S = Q K^T (Q pre-scaled); 16 MMAs, kk outer
        float sc[4][4];
#pragma unroll
        for (int n8 = 0; n8 < 4; n8++)
            sc[n8][0] = sc[n8][1] = sc[n8][2] = sc[n8][3] = 0.0f;
#pragma unroll
        for (int kk = 0; kk < 4; kk++) {
#pragma unroll
            for (int n8 = 0; n8 < 4; n8++) {
                unsigned bb[2];
                bb[0] = __float_as_uint(Ks[(n8 * 8 + g) * 36 + kk * 8 + t    ]);
                bb[1] = __float_as_uint(Ks[(n8 * 8 + g) * 36 + kk * 8 + t + 4]);
                MMA_TF32(sc[n8], qa[kk], bb);
            }
        }

        // 3. combine biases (SW128-swizzled TMA stage) + mask (regs)
#pragma unroll
        for (int n8 = 0; n8 < 4; n8++) {
            int fc   = n8 * 8 + 2 * t;
            int cidx = fc ^ xr;
            int i0 = r0i * 32 + cidx;
            int i1 = (r0i + 8) * 32 + cidx;
            float2 e0 = *(const float2*)&BB[i0];
            float2 e1 = *(const float2*)&BB[i1];
            float2 s0 = *(const float2*)&BB[2048 + i0];
            float2 s1 = *(const float2*)&BB[2048 + i1];
            float2 r0 = *(const float2*)&BB[4096 + i0];
            float2 r1 = *(const float2*)&BB[4096 + i1];
            float2 mk = mkc[n8];
            sc[n8][0] += (e0.x + s0.x) + (r0.x + mk.x);
            sc[n8][1] += (e0.y + s0.y) + (r0.y + mk.y);
            sc[n8][2] += (e1.x + s1.x) + (r1.x + mk.x);
            sc[n8][3] += (e1.y + s1.y) + (r1.y + mk.y);
        }

        // 4. online softmax (32-key tile)
        float ml0 = sc[0][0], ml1 = sc[0][2];
#pragma unroll
        for (int n8 = 0; n8 < 4; n8++) {
            ml0 = fmaxf(ml0, fmaxf(sc[n8][0], sc[n8][1]));
            ml1 = fmaxf(ml1, fmaxf(sc[n8][2], sc[n8][3]));
        }
        ml0 = fmaxf(ml0, __shfl_xor_sync(0xffffffffu, ml0, 1));
        ml0 = fmaxf(ml0, __shfl_xor_sync(0xffffffffu, ml0, 2));
        ml1 = fmaxf(ml1, __shfl_xor_sync(0xffffffffu, ml1, 1));
        ml1 = fmaxf(ml1, __shfl_xor_sync(0xffffffffu, ml1, 2));

        float mn0 = fmaxf(m0, ml0);
        float mn1 = fmaxf(m1, ml1);
        float mc0 = fmaxf(mn0, -1e30f);
        float mc1 = fmaxf(mn1, -1e30f);
        float rs0 = __expf(fmaxf(m0, -1e30f) - mc0);
        float rs1 = __expf(fmaxf(m1, -1e30f) - mc1);
        m0 = mn0; m1 = mn1;

        float sum0 = 0.0f, sum1 = 0.0f;
#pragma unroll
        for (int n8 = 0; n8 < 4; n8++) {
            float p0 = __expf(sc[n8][0] - mc0);
            float p1 = __expf(sc[n8][1] - mc0);
            float p2 = __expf(sc[n8][2] - mc1);
            float p3 = __expf(sc[n8][3] - mc1);
            sum0 += p0 + p1;
            sum1 += p2 + p3;
            float2 w0, w1;
            w0.x = __uint_as_float(f2tf32(p0)); w0.y = __uint_as_float(f2tf32(p1));
            w1.x = __uint_as_float(f2tf32(p2)); w1.y = __uint_as_float(f2tf32(p3));
            *(float2*)&Ps[(w16 + g    ) * 36 + n8 * 8 + 2 * t] = w0;
            *(float2*)&Ps[(w16 + g + 8) * 36 + n8 * 8 + 2 * t] = w1;
        }
        sum0 += __shfl_xor_sync(0xffffffffu, sum0, 1);
        sum0 += __shfl_xor_sync(0xffffffffu, sum0, 2);
        sum1 += __shfl_xor_sync(0xffffffffu, sum1, 1);
        sum1 += __shfl_xor_sync(0xffffffffu, sum1, 2);
        l0 = l0 * rs0 + sum0;
        l1 = l1 * rs1 + sum1;

#pragma unroll
        for (int n = 0; n < 4; n++) {
            o[n][0] *= rs0; o[n][1] *= rs0;
            o[n][2] *= rs1; o[n][3] *= rs1;
        }

        __syncwarp();   // this warp's Ps rows visible warp-wide

        // 5. O += P V (16 MMAs)
#pragma unroll
        for (int kk = 0; kk < 4; kk++) {
            unsigned pa[4];
            pa[0] = __float_as_uint(Ps[(w16 + g    ) * 36 + kk * 8 + t    ]);
            pa[1] = __float_as_uint(Ps[(w16 + g + 8) * 36 + kk * 8 + t    ]);
            pa[2] = __float_as_uint(Ps[(w16 + g    ) * 36 + kk * 8 + t + 4]);
            pa[3] = __float_as_uint(Ps[(w16 + g + 8) * 36 + kk * 8 + t + 4]);
#pragma unroll
            for (int n = 0; n < 4; n++) {
                unsigned vb[2];
                vb[0] = __float_as_uint(Vs[(kk * 8 + t    ) * 40 + n * 8 + g]);
                vb[1] = __float_as_uint(Vs[(kk * 8 + t + 4) * 40 + n * 8 + g]);
                MMA_TF32(o[n], pa, vb);
            }
        }

        // 6. tile i fully consumed by ALL warps -> refill slot with i+2
        __syncthreads();
        if (i + 2 <= 31) {
            issue_kv(i + 2);
            tma_bias(i + 2);
        }
        if (i + 1 <= 31) {
#pragma unroll
            for (int n8 = 0; n8 < 4; n8++)
                mkc[n8] = *(const float2*)&maskp[(i + 1) * 32 + n8 * 8 + 2 * t];
        }
    }

    // normalize + scatter (tf32-rounded for the O-projection mma)
    float inv0 = (l0 > 0.0f) ? (1.0f / l0) : 0.0f;
    float inv1 = (l1 > 0.0f) ? (1.0f / l1) : 0.0f;
    const int r0 = qb + w16 + g;
    const int r1 = r0 + 8;
#pragma unroll
    for (int n = 0; n < 4; n++) {
        int d = n * 8 + 2 * t;
        float2 v0, v1;
        v0.x = __uint_as_float(f2tf32(o[n][0] * inv0));
        v0.y = __uint_as_float(f2tf32(o[n][1] * inv0));
        v1.x = __uint_as_float(f2tf32(o[n][2] * inv1));
        v1.y = __uint_as_float(f2tf32(o[n][3] * inv1));
        *(float2*)&g_AO[((size_t)(b * N_SEQ + r0)) * D_MODEL + h * D_HEAD + d] = v0;
        *(float2*)&g_AO[((size_t)(b * N_SEQ + r1)) * D_MODEL + h * D_HEAD + d] = v1;
    }
}

// ---------------------------------------------------------------------------
typedef CUresult (*PFN_tmeTiled)(
    CUtensorMap*, CUtensorMapDataType, cuuint32_t, void*,
    const cuuint64_t*, const cuuint64_t*, const cuuint32_t*, const cuuint32_t*,
    CUtensorMapInterleave, CUtensorMapSwizzle, CUtensorMapL2promotion,
    CUtensorMapFloatOOBfill);

static void encode_bias_map(PFN_tmeTiled fn, CUtensorMap* tm, const void* ptr) {
    cuuint64_t dims[2]    = { (cuuint64_t)N_SEQ, (cuuint64_t)(BATCH * N_HEADS * N_SEQ) };
    cuuint64_t strides[1] = { (cuuint64_t)N_SEQ * sizeof(float) };
    cuuint32_t box[2]     = { 32u, 64u };
    cuuint32_t estr[2]    = { 1u, 1u };
    fn(tm, CU_TENSOR_MAP_DATA_TYPE_FLOAT32, 2, (void*)ptr,
       dims, strides, box, estr,
       CU_TENSOR_MAP_INTERLEAVE_NONE, CU_TENSOR_MAP_SWIZZLE_128B,
       CU_TENSOR_MAP_L2_PROMOTION_L2_128B, CU_TENSOR_MAP_FLOAT_OOB_FILL_NONE);
}

extern "C" void kernel_launch(void* const* d_in, const int* in_sizes, int n_in,
                              void* d_out, int out_size)
{
    const float* x    = (const float*)d_in[0];
    const float* edge = (const float*)d_in[1];
    const float* spat = (const float*)d_in[2];
    const float* rnk  = (const float*)d_in[3];
    const void*  mask = d_in[4];
    const float* Wq = (const float*)d_in[5];
    const float* bq = (const float*)d_in[6];
    const float* Wk = (const float*)d_in[7];
    const float* bk = (const float*)d_in[8];
    const float* Wv = (const float*)d_in[9];
    const float* bv = (const float*)d_in[10];
    const float* Wo = (const float*)d_in[11];
    const float* bo = (const float*)d_in[12];

    PFN_tmeTiled fn = nullptr;
    cudaDriverEntryPointQueryResult qres;
    cudaGetDriverEntryPoint("cuTensorMapEncodeTiled", (void**)&fn,
                            cudaEnableDefault, &qres);

    CUtensorMap tmE, tmS, tmR;
    encode_bias_map(fn, &tmE, edge);
    encode_bias_map(fn, &tmS, spat);
    encode_bias_map(fn, &tmR, rnk);

    cudaFuncSetAttribute(attn_tc_kernel,
                         cudaFuncAttributeMaxDynamicSharedMemorySize,
                         ATTN_SMEM_BYTES);
    cudaFuncSetAttribute(gemm_qkv_tc,
                         cudaFuncAttributeMaxDynamicSharedMemorySize,
                         GEMM_SMEM_BYTES);
    cudaFuncSetAttribute(gemm_o_tc,
                         cudaFuncAttributeMaxDynamicSharedMemorySize,
                         GEMM_SMEM_BYTES);

    gemm_qkv_tc<<<dim3(32, 4, 3), 256, GEMM_SMEM_BYTES>>>(
        x, Wq, Wk, Wv, bq, bk, bv, mask);

    attn_tc_kernel<<<dim3(16, 32), 128, ATTN_SMEM_BYTES>>>(tmE, tmS, tmR);

    gemm_o_tc<<<dim3(32, 4), 256, GEMM_SMEM_BYTES>>>(Wo, bo, (float*)d_out);
}

// round 17
// speedup vs baseline: 1.1834x; 1.0445x over previous
#include <cuda_runtime.h>
#include <cuda.h>
#include <math.h>

#define BATCH   4
#define N_SEQ   1024
#define D_MODEL 256
#define N_HEADS 8
#define D_HEAD  32
#define ATT_SCALE 0.17677669529663687f   // 1/sqrt(32)

// Scratch (device globals: no allocation allowed in kernel_launch)
__device__ float g_Q[BATCH * N_HEADS * N_SEQ * D_HEAD];   // [b,h,n,dk]  tf32, pre-scaled
__device__ float g_K[BATCH * N_HEADS * N_SEQ * D_HEAD];   // tf32-rounded
__device__ float g_V[BATCH * N_HEADS * N_SEQ * D_HEAD];   // tf32-rounded
__device__ float g_AO[BATCH * N_SEQ * D_MODEL];           // attention out, tf32-rounded
__device__ float g_maskval[BATCH * N_SEQ];                // 0 or -inf per key

__device__ __forceinline__ unsigned f2tf32(float f) {
    unsigned u;
    asm("cvt.rna.tf32.f32 %0, %1;" : "=r"(u) : "f"(f));
    return u;
}

#define MMA_TF32(d, a, b)                                                     \
    asm volatile(                                                             \
        "mma.sync.aligned.m16n8k8.row.col.f32.tf32.tf32.f32 "                 \
        "{%0,%1,%2,%3}, {%4,%5,%6,%7}, {%8,%9}, {%0,%1,%2,%3};\n"             \
        : "+f"((d)[0]), "+f"((d)[1]), "+f"((d)[2]), "+f"((d)[3])              \
        : "r"((a)[0]), "r"((a)[1]), "r"((a)[2]), "r"((a)[3]),                 \
          "r"((b)[0]), "r"((b)[1]))

__device__ __forceinline__ void cp_async16(void* s, const void* g) {
    unsigned sa = (unsigned)__cvta_generic_to_shared(s);
    asm volatile("cp.async.cg.shared.global [%0], [%1], 16;" :: "r"(sa), "l"(g));
}
#define CP_COMMIT() asm volatile("cp.async.commit_group;")
#define CP_WAIT0()  asm volatile("cp.async.wait_group 0;")
#define CP_WAIT1()  asm volatile("cp.async.wait_group 1;")

__device__ __forceinline__ void mbar_init(unsigned mbar, unsigned cnt) {
    asm volatile("mbarrier.init.shared.b64 [%0], %1;" :: "r"(mbar), "r"(cnt) : "memory");
}
__device__ __forceinline__ void mbar_expect_tx(unsigned mbar, unsigned bytes) {
    asm volatile("mbarrier.arrive.expect_tx.shared.b64 _, [%0], %1;"
                 :: "r"(mbar), "r"(bytes) : "memory");
}
__device__ __forceinline__ void mbar_wait(unsigned mbar, unsigned phase) {
    asm volatile(
        "{\n\t.reg .pred P1;\n\t"
        "WAIT_LOOP_%=:\n\t"
        "mbarrier.try_wait.parity.acquire.cta.shared::cta.b64 P1, [%0], %1, 0x989680;\n\t"
        "@P1 bra.uni WAIT_DONE_%=;\n\t"
        "bra.uni WAIT_LOOP_%=;\n\t"
        "WAIT_DONE_%=:\n\t}"
        :: "r"(mbar), "r"(phase) : "memory");
}
__device__ __forceinline__ void tma2d(unsigned dst, const CUtensorMap* m,
                                      int x, int y, unsigned mbar) {
    asm volatile(
        "cp.async.bulk.tensor.2d.shared::cta.global.tile.mbarrier::complete_tx::bytes "
        "[%0], [%1, {%2, %3}], [%4];"
        :: "r"(dst), "l"(m), "r"(x), "r"(y), "r"(mbar) : "memory");
}

// ---------------------------------------------------------------------------
// QKV projection (round-15). grid=(32,4,3), block=256, mask prep folded.
// ---------------------------------------------------------------------------
#define GEMM_SMEM_BYTES (13824 * 4)

__global__ __launch_bounds__(256) void gemm_qkv_tc(
    const float* __restrict__ x,
    const float* __restrict__ Wq, const float* __restrict__ Wk, const float* __restrict__ Wv,
    const float* __restrict__ bq, const float* __restrict__ bk, const float* __restrict__ bv,
    const void* __restrict__ mraw)
{
    extern __shared__ float sm[];
    float* As = sm;            // [2][128][36]
    float* Ws = sm + 9216;     // [2][64][36]

    if (blockIdx.x == 0 && blockIdx.y == 0 && blockIdx.z == 0) {
        const int tid = threadIdx.x;
        const unsigned* mi = (const unsigned*)mraw;
        int ok_int = 1, ok_float = 1;
        for (int i = tid; i < 1024; i += 256) {
            unsigned v = mi[i];
            if (v > 1u) ok_int = 0;
            if (v != 0u && v != 0x3F800000u) ok_float = 0;
        }
        int all_int   = __syncthreads_and(ok_int);
        int all_float = __syncthreads_and(ok_float);
        const int mode = all_int ? 0 : (all_float ? 1 : 2);
        const float NEG_INF = __int_as_float(0xff800000);
        for (int i = tid; i < BATCH * N_SEQ; i += 256) {
            int masked;
            if (mode == 0)      masked = ((const int*)mraw)[i] != 0;
            else if (mode == 1) masked = ((const unsigned*)mraw)[i] != 0u;
            else                masked = ((const unsigned char*)mraw)[i] != 0;
            g_maskval[i] = masked ? NEG_INF : 0.0f;
        }
    }

    const int z = blockIdx.z;
    const float* W    = (z == 0) ? Wq : (z == 1) ? Wk : Wv;
    const float* bias = (z == 0) ? bq : (z == 1) ? bk : bv;
    float* out        = (z == 0) ? g_Q : (z == 1) ? g_K : g_V;

    const int tid  = threadIdx.x;
    const int lane = tid & 31;
    const int w    = tid >> 5;
    const int g    = lane >> 2;
    const int t    = lane & 3;
    const int w16  = w * 16;
    const int rbase = blockIdx.x * 128;
    const int cbase = blockIdx.y * 64;

    float sc[8][4];
#pragma unroll
    for (int n = 0; n < 8; n++)
#pragma unroll
        for (int j = 0; j < 4; j++) sc[n][j] = 0.0f;

    auto prefetch = [&](int c) {
        const int k0 = c * 32, st = c & 1;
        float* Ap = As + st * 4608;
        float* Wp = Ws + st * 2304;
#pragma unroll
        for (int it = 0; it < 4; it++) {
            int s = it * 256 + tid;
            int row = s >> 3;
            int c4 = (s & 7) * 4;
            cp_async16(&Ap[row * 36 + c4], &x[(size_t)(rbase + row) * D_MODEL + k0 + c4]);
        }
#pragma unroll
        for (int it = 0; it < 2; it++) {
            int s = it * 256 + tid;
            int row = s >> 3;
            int c4 = (s & 7) * 4;
            cp_async16(&Wp[row * 36 + c4], &W[(size_t)(cbase + row) * D_MODEL + k0 + c4]);
        }
        CP_COMMIT();
    };

    prefetch(0);
    for (int c = 0; c < 8; c++) {
        const int st = c & 1;
        const float* Ap = As + st * 4608;
        const float* Wp = Ws + st * 2304;
        if (c < 7) { prefetch(c + 1); CP_WAIT1(); }
        else       { CP_WAIT0(); }
        __syncthreads();

        unsigned qa[4][4];
#pragma unroll
        for (int kk = 0; kk < 4; kk++) {
            qa[kk][0] = f2tf32(Ap[(w16 + g    ) * 36 + kk * 8 + t    ]);
            qa[kk][1] = f2tf32(Ap[(w16 + g + 8) * 36 + kk * 8 + t    ]);
            qa[kk][2] = f2tf32(Ap[(w16 + g    ) * 36 + kk * 8 + t + 4]);
            qa[kk][3] = f2tf32(Ap[(w16 + g + 8) * 36 + kk * 8 + t + 4]);
        }
#pragma unroll
        for (int kk = 0; kk < 4; kk++) {
#pragma unroll
            for (int n8 = 0; n8 < 8; n8++) {
                unsigned bb[2];
                bb[0] = f2tf32(Wp[(n8 * 8 + g) * 36 + kk * 8 + t    ]);
                bb[1] = f2tf32(Wp[(n8 * 8 + g) * 36 + kk * 8 + t + 4]);
                MMA_TF32(sc[n8], qa[kk], bb);
            }
        }
        __syncthreads();
    }

    const float scale = (z == 0) ? ATT_SCALE : 1.0f;
#pragma unroll
    for (int n8 = 0; n8 < 8; n8++) {
        int c0 = cbase + n8 * 8 + 2 * t;
        float b0v = bias[c0], b1v = bias[c0 + 1];
        int r0 = rbase + w16 + g;
        int r1 = r0 + 8;
        float2 v0, v1;
        v0.x = __uint_as_float(f2tf32((sc[n8][0] + b0v) * scale));
        v0.y = __uint_as_float(f2tf32((sc[n8][1] + b1v) * scale));
        v1.x = __uint_as_float(f2tf32((sc[n8][2] + b0v) * scale));
        v1.y = __uint_as_float(f2tf32((sc[n8][3] + b1v) * scale));
        int h = c0 >> 5, dk = c0 & 31;
        int b0i = r0 >> 10, n0 = r0 & 1023;
        int b1i = r1 >> 10, n1 = r1 & 1023;
        *(float2*)&out[(size_t)(((b0i << 3) + h) * N_SEQ + n0) * D_HEAD + dk] = v0;
        *(float2*)&out[(size_t)(((b1i << 3) + h) * N_SEQ + n1) * D_HEAD + dk] = v1;
    }
}

// ---------------------------------------------------------------------------
// Output projection (round-15). grid=(32,4), block=256.
// ---------------------------------------------------------------------------
__global__ __launch_bounds__(256) void gemm_o_tc(
    const float* __restrict__ W, const float* __restrict__ bias,
    float* __restrict__ out)
{
    extern __shared__ float sm[];
    float* As = sm;
    float* Ws = sm + 9216;

    const int tid  = threadIdx.x;
    const int lane = tid & 31;
    const int w    = tid >> 5;
    const int g    = lane >> 2;
    const int t    = lane & 3;
    const int w16  = w * 16;
    const int rbase = blockIdx.x * 128;
    const int cbase = blockIdx.y * 64;

    float sc[8][4];
#pragma unroll
    for (int n = 0; n < 8; n++)
#pragma unroll
        for (int j = 0; j < 4; j++) sc[n][j] = 0.0f;

    auto prefetch = [&](int c) {
        const int k0 = c * 32, st = c & 1;
        float* Ap = As + st * 4608;
        float* Wp = Ws + st * 2304;
#pragma unroll
        for (int it = 0; it < 4; it++) {
            int s = it * 256 + tid;
            int row = s >> 3;
            int c4 = (s & 7) * 4;
            cp_async16(&Ap[row * 36 + c4], &g_AO[(size_t)(rbase + row) * D_MODEL + k0 + c4]);
        }
#pragma unroll
        for (int it = 0; it < 2; it++) {
            int s = it * 256 + tid;
            int row = s >> 3;
            int c4 = (s & 7) * 4;
            cp_async16(&Wp[row * 36 + c4], &W[(size_t)(cbase + row) * D_MODEL + k0 + c4]);
        }
        CP_COMMIT();
    };

    prefetch(0);
    for (int c = 0; c < 8; c++) {
        const int st = c & 1;
        const float* Ap = As + st * 4608;
        const float* Wp = Ws + st * 2304;
        if (c < 7) { prefetch(c + 1); CP_WAIT1(); }
        else       { CP_WAIT0(); }
        __syncthreads();

        unsigned qa[4][4];
#pragma unroll
        for (int kk = 0; kk < 4; kk++) {
            qa[kk][0] = __float_as_uint(Ap[(w16 + g    ) * 36 + kk * 8 + t    ]);
            qa[kk][1] = __float_as_uint(Ap[(w16 + g + 8) * 36 + kk * 8 + t    ]);
            qa[kk][2] = __float_as_uint(Ap[(w16 + g    ) * 36 + kk * 8 + t + 4]);
            qa[kk][3] = __float_as_uint(Ap[(w16 + g + 8) * 36 + kk * 8 + t + 4]);
        }
#pragma unroll
        for (int kk = 0; kk < 4; kk++) {
#pragma unroll
            for (int n8 = 0; n8 < 8; n8++) {
                unsigned bb[2];
                bb[0] = f2tf32(Wp[(n8 * 8 + g) * 36 + kk * 8 + t    ]);
                bb[1] = f2tf32(Wp[(n8 * 8 + g) * 36 + kk * 8 + t + 4]);
                MMA_TF32(sc[n8], qa[kk], bb);
            }
        }
        __syncthreads();
    }

#pragma unroll
    for (int n8 = 0; n8 < 8; n8++) {
        int c0 = cbase + n8 * 8 + 2 * t;
        float b0v = bias[c0], b1v = bias[c0 + 1];
        int r0 = rbase + w16 + g;
        int r1 = r0 + 8;
        float2 v0, v1;
        v0.x = sc[n8][0] + b0v;  v0.y = sc[n8][1] + b1v;
        v1.x = sc[n8][2] + b0v;  v1.y = sc[n8][3] + b1v;
        *(float2*)&out[(size_t)r0 * D_MODEL + c0] = v0;
        *(float2*)&out[(size_t)r1 * D_MODEL + c0] = v1;
    }
}

// ---------------------------------------------------------------------------
// Tensor-core flash attention — TMA bias streaming, TRIPLE-buffered stage,
// 2 CTAs/SM. grid=(16,32), block=128. k-tile = 32 keys, 32 iterations.
// Bias: 3 TMA loads/tile (box 32x64, SW128) into slot i%3, mbarrier phase
// (i/3)&1, issued 3 tiles ahead (2-tile lead in steady state).
// K/V: cp.async double-buffered, 2-tiles-ahead commit groups.
// Dynamic smem (floats):
//   Bias[3][3][2048] @ 0     (18432)   slot stride 6144; E/S/R at +0/+2048/+4096
//   KsB [2][32*36]   @ 18432 (2304)
//   VsB [2][32*40]   @ 20736 (2560)
//   Ps  [64*36]      @ 23296 (2304)
//   mbar[3]          @ 25600 (6)
// total 25606 floats = 102424 B  -> 2 CTAs/SM.
// ---------------------------------------------------------------------------
#define ATTN_SMEM_BYTES (25606 * 4)

__global__ __launch_bounds__(128) void attn_tc_kernel(
    const __grid_constant__ CUtensorMap tmE,
    const __grid_constant__ CUtensorMap tmS,
    const __grid_constant__ CUtensorMap tmR)
{
    extern __shared__ float dsm[];
    float* KsB = dsm + 18432;
    float* VsB = dsm + 20736;
    float* Ps  = dsm + 23296;

    const unsigned smem_u32 = (unsigned)__cvta_generic_to_shared(dsm);
    const unsigned mbar_base = smem_u32 + 25600u * 4u;

    const int tid  = threadIdx.x;
    const int lane = tid & 31;
    const int w    = tid >> 5;
    const int g    = lane >> 2;
    const int t    = lane & 3;
    const int qb   = blockIdx.x * 64;
    const int bh   = blockIdx.y;
    const int b    = bh >> 3;
    const int h    = bh & 7;
    const int w16  = w * 16;

    const float* Kg0 = g_K + (size_t)bh * N_SEQ * D_HEAD;
    const float* Vg0 = g_V + (size_t)bh * N_SEQ * D_HEAD;
    const float* maskp = g_maskval + b * N_SEQ;
    const int yrow = bh * N_SEQ + qb;

    if (tid == 0) {
        mbar_init(mbar_base,      1);
        mbar_init(mbar_base + 8,  1);
        mbar_init(mbar_base + 16, 1);
    }
    __syncthreads();

    // TMA bias group for k-tile i into slot i%3 (24576 bytes expected)
    auto tma_bias = [&](int i) {
        if (tid == 0) {
            const int slot = i % 3;
            const unsigned mb = mbar_base + slot * 8;
            const unsigned sb = smem_u32 + (unsigned)(slot * 6144) * 4u;
            mbar_expect_tx(mb, 24576u);
            tma2d(sb,          &tmE, i * 32, yrow, mb);
            tma2d(sb + 8192u,  &tmS, i * 32, yrow, mb);
            tma2d(sb + 16384u, &tmR, i * 32, yrow, mb);
        }
    };
    // cp.async K/V for k-tile i into slot i&1 (own commit group)
    auto issue_kv = [&](int i) {
        const int kb = i * 32;
        const int slot = i & 1;
        const float* Kg = Kg0 + (size_t)kb * D_HEAD;
        const float* Vg = Vg0 + (size_t)kb * D_HEAD;
        float* Ka = KsB + slot * 1152;
        float* Va = VsB + slot * 1280;
#pragma unroll
        for (int it = 0; it < 2; it++) {
            int s = it * 128 + tid;     // 0..255
            int row = s >> 3;           // 0..31
            int c4 = (s & 7) * 4;
            cp_async16(&Ka[row * 36 + c4], &Kg[row * D_HEAD + c4]);
            cp_async16(&Va[row * 40 + c4], &Vg[row * D_HEAD + c4]);
        }
        CP_COMMIT();
    };

    // ---- Prologue: bias(0..2) TMA; KV(0),(1); Q stage; drain cp.async ----
    tma_bias(0);
    tma_bias(1);
    tma_bias(2);
    issue_kv(0);
    issue_kv(1);
    const float* Qg = g_Q + ((size_t)bh * N_SEQ + qb) * D_HEAD;
#pragma unroll
    for (int it = 0; it < 4; it++) {
        int s = it * 128 + tid;         // 0..511
        int row = s >> 3;               // 0..63
        int c4 = (s & 7) * 4;
        cp_async16(&Ps[row * 36 + c4], &Qg[row * D_HEAD + c4]);
    }
    CP_COMMIT();
    CP_WAIT0();
    __syncthreads();

    unsigned qa[4][4];
#pragma unroll
    for (int kk = 0; kk < 4; kk++) {
        qa[kk][0] = __float_as_uint(Ps[(w16 + g    ) * 36 + kk * 8 + t    ]);
        qa[kk][1] = __float_as_uint(Ps[(w16 + g + 8) * 36 + kk * 8 + t    ]);
        qa[kk][2] = __float_as_uint(Ps[(w16 + g    ) * 36 + kk * 8 + t + 4]);
        qa[kk][3] = __float_as_uint(Ps[(w16 + g + 8) * 36 + kk * 8 + t + 4]);
    }
    __syncthreads();   // all warps hold Q frags before Ps reused for P

    float2 mkc[4];
#pragma unroll
    for (int n8 = 0; n8 < 4; n8++)
        mkc[n8] = *(const float2*)&maskp[n8 * 8 + 2 * t];

    float o[4][4];
#pragma unroll
    for (int n = 0; n < 4; n++)
#pragma unroll
        for (int j = 0; j < 4; j++) o[n][j] = 0.0f;

    float m0 = __int_as_float(0xff800000), m1 = m0;
    float l0 = 0.0f, l1 = 0.0f;

    const int r0i = w16 + g;           // q row (0..63) within this CTA's tile
    const int xr  = (r0i & 7) << 2;    // SW128 float-col XOR (same for r0i+8)

    for (int i = 0; i < 32; i++) {
        const int kslot = i & 1;
        const int bslot = i % 3;
        float* Ks = KsB + kslot * 1152;
        float* Vs = VsB + kslot * 1280;
        const float* BB = dsm + bslot * 6144;

        // 1. KV(i) complete (KV(i+1) may stay in flight); bias(i) TMA done
        if (i == 31) { CP_WAIT0(); } else { CP_WAIT1(); }
        mbar_wait(mbar_base + bslot * 8, (unsigned)((i / 3) & 1));
        __syncthreads();

        // 2. S = Q K^T (Q pre-scaled); 16 MMAs, kk outer
        float sc[4][4];
#pragma unroll
        for (int n8 = 0; n8 < 4; n8++)
            sc[n8][0] = sc[n8][1] = sc[n8][2] = sc[n8][3] = 0.0f;
#pragma unroll
        for (int kk = 0; kk < 4; kk++) {
#pragma unroll
            for (int n8 = 0; n8 < 4; n8++) {
                unsigned bb[2];
                bb[0] = __float_as_uint(Ks[(n8 * 8 + g) * 36 + kk * 8 + t    ]);
                bb[1] = __float_as_uint(Ks[(n8 * 8 + g) * 36 + kk * 8 + t + 4]);
                MMA_TF32(sc[n8], qa[kk], bb);
            }
        }

        // 3. combine biases (SW128-swizzled TMA stage) + mask (regs)
#pragma unroll
        for (int n8 = 0; n8 < 4; n8++) {
            int fc   = n8 * 8 + 2 * t;
            int cidx = fc ^ xr;
            int i0 = r0i * 32 + cidx;
            int i1 = (r0i + 8) * 32 + cidx;
            float2 e0 = *(const float2*)&BB[i0];
            float2 e1 = *(const float2*)&BB[i1];
            float2 s0 = *(const float2*)&BB[2048 + i0];
            float2 s1 = *(const float2*)&BB[2048 + i1];
            float2 r0 = *(const float2*)&BB[4096 + i0];
            float2 r1 = *(const float2*)&BB[4096 + i1];
            float2 mk = mkc[n8];
            sc[n8][0] += (e0.x + s0.x) + (r0.x + mk.x);
            sc[n8][1] += (e0.y + s0.y) + (r0.y + mk.y);
            sc[n8][2] += (e1.x + s1.x) + (r1.x + mk.x);
            sc[n8][3] += (e1.y + s1.y) + (r1.y + mk.y);
        }

        // 4. online softmax (32-key tile)
        float ml0 = sc[0][0], ml1 = sc[0][2];
#pragma unroll
        for (int n8 = 0; n8 < 4; n8++) {
            ml0 = fmaxf(ml0, fmaxf(sc[n8][0], sc[n8][1]));
            ml1 = fmaxf(ml1, fmaxf(sc[n8][2], sc[n8][3]));
        }
        ml0 = fmaxf(ml0, __shfl_xor_sync(0xffffffffu, ml0, 1));
        ml0 = fmaxf(ml0, __shfl_xor_sync(0xffffffffu, ml0, 2));
        ml1 = fmaxf(ml1, __shfl_xor_sync(0xffffffffu, ml1, 1));
        ml1 = fmaxf(ml1, __shfl_xor_sync(0xffffffffu, ml1, 2));

        float mn0 = fmaxf(m0, ml0);
        float mn1 = fmaxf(m1, ml1);
        float mc0 = fmaxf(mn0, -1e30f);
        float mc1 = fmaxf(mn1, -1e30f);
        float rs0 = __expf(fmaxf(m0, -1e30f) - mc0);
        float rs1 = __expf(fmaxf(m1, -1e30f) - mc1);
        m0 = mn0; m1 = mn1;

        float sum0 = 0.0f, sum1 = 0.0f;
#pragma unroll
        for (int n8 = 0; n8 < 4; n8++) {
            float p0 = __expf(sc[n8][0] - mc0);
            float p1 = __expf(sc[n8][1] - mc0);
            float p2 = __expf(sc[n8][2] - mc1);
            float p3 = __expf(sc[n8][3] - mc1);
            sum0 += p0 + p1;
            sum1 += p2 + p3;
            float2 w0, w1;
            w0.x = __uint_as_float(f2tf32(p0)); w0.y = __uint_as_float(f2tf32(p1));
            w1.x = __uint_as_float(f2tf32(p2)); w1.y = __uint_as_float(f2tf32(p3));
            *(float2*)&Ps[(w16 + g    ) * 36 + n8 * 8 + 2 * t] = w0;
            *(float2*)&Ps[(w16 + g + 8) * 36 + n8 * 8 + 2 * t] = w1;
        }
        sum0 += __shfl_xor_sync(0xffffffffu, sum0, 1);
        sum0 += __shfl_xor_sync(0xffffffffu, sum0, 2);
        sum1 += __shfl_xor_sync(0xffffffffu, sum1, 1);
        sum1 += __shfl_xor_sync(0xffffffffu, sum1, 2);
        l0 = l0 * rs0 + sum0;
        l1 = l1 * rs1 + sum1;

#pragma unroll
        for (int n = 0; n < 4; n++) {
            o[n][0] *= rs0; o[n][1] *= rs0;
            o[n][2] *= rs1; o[n][3] *= rs1;
        }

        __syncwarp();   // this warp's Ps rows visible warp-wide

        // 5. O += P V (16 MMAs)
#pragma unroll
        for (int kk = 0; kk < 4; kk++) {
            unsigned pa[4];
            pa[0] = __float_as_uint(Ps[(w16 + g    ) * 36 + kk * 8 + t    ]);
            pa[1] = __float_as_uint(Ps[(w16 + g + 8) * 36 + kk * 8 + t    ]);
            pa[2] = __float_as_uint(Ps[(w16 + g    ) * 36 + kk * 8 + t + 4]);
            pa[3] = __float_as_uint(Ps[(w16 + g + 8) * 36 + kk * 8 + t + 4]);
#pragma unroll
            for (int n = 0; n < 4; n++) {
                unsigned vb[2];
                vb[0] = __float_as_uint(Vs[(kk * 8 + t    ) * 40 + n * 8 + g]);
                vb[1] = __float_as_uint(Vs[(kk * 8 + t + 4) * 40 + n * 8 + g]);
                MMA_TF32(o[n], pa, vb);
            }
        }

        // 6. tile i fully consumed by ALL warps -> refill slots
        __syncthreads();
        if (i + 2 <= 31) issue_kv(i + 2);
        if (i + 3 <= 31) tma_bias(i + 3);
        if (i + 1 <= 31) {
#pragma unroll
            for (int n8 = 0; n8 < 4; n8++)
                mkc[n8] = *(const float2*)&maskp[(i + 1) * 32 + n8 * 8 + 2 * t];
        }
    }

    // normalize + scatter (tf32-rounded for the O-projection mma)
    float inv0 = (l0 > 0.0f) ? (1.0f / l0) : 0.0f;
    float inv1 = (l1 > 0.0f) ? (1.0f / l1) : 0.0f;
    const int r0 = qb + w16 + g;
    const int r1 = r0 + 8;
#pragma unroll
    for (int n = 0; n < 4; n++) {
        int d = n * 8 + 2 * t;
        float2 v0, v1;
        v0.x = __uint_as_float(f2tf32(o[n][0] * inv0));
        v0.y = __uint_as_float(f2tf32(o[n][1] * inv0));
        v1.x = __uint_as_float(f2tf32(o[n][2] * inv1));
        v1.y = __uint_as_float(f2tf32(o[n][3] * inv1));
        *(float2*)&g_AO[((size_t)(b * N_SEQ + r0)) * D_MODEL + h * D_HEAD + d] = v0;
        *(float2*)&g_AO[((size_t)(b * N_SEQ + r1)) * D_MODEL + h * D_HEAD + d] = v1;
    }
}

// ---------------------------------------------------------------------------
typedef CUresult (*PFN_tmeTiled)(
    CUtensorMap*, CUtensorMapDataType, cuuint32_t, void*,
    const cuuint64_t*, const cuuint64_t*, const cuuint32_t*, const cuuint32_t*,
    CUtensorMapInterleave, CUtensorMapSwizzle, CUtensorMapL2promotion,
    CUtensorMapFloatOOBfill);

static void encode_bias_map(PFN_tmeTiled fn, CUtensorMap* tm, const void* ptr) {
    cuuint64_t dims[2]    = { (cuuint64_t)N_SEQ, (cuuint64_t)(BATCH * N_HEADS * N_SEQ) };
    cuuint64_t strides[1] = { (cuuint64_t)N_SEQ * sizeof(float) };
    cuuint32_t box[2]     = { 32u, 64u };
    cuuint32_t estr[2]    = { 1u, 1u };
    fn(tm, CU_TENSOR_MAP_DATA_TYPE_FLOAT32, 2, (void*)ptr,
       dims, strides, box, estr,
       CU_TENSOR_MAP_INTERLEAVE_NONE, CU_TENSOR_MAP_SWIZZLE_128B,
       CU_TENSOR_MAP_L2_PROMOTION_L2_128B, CU_TENSOR_MAP_FLOAT_OOB_FILL_NONE);
}

extern "C" void kernel_launch(void* const* d_in, const int* in_sizes, int n_in,
                              void* d_out, int out_size)
{
    const float* x    = (const float*)d_in[0];
    const float* edge = (const float*)d_in[1];
    const float* spat = (const float*)d_in[2];
    const float* rnk  = (const float*)d_in[3];
    const void*  mask = d_in[4];
    const float* Wq = (const float*)d_in[5];
    const float* bq = (const float*)d_in[6];
    const float* Wk = (const float*)d_in[7];
    const float* bk = (const float*)d_in[8];
    const float* Wv = (const float*)d_in[9];
    const float* bv = (const float*)d_in[10];
    const float* Wo = (const float*)d_in[11];
    const float* bo = (const float*)d_in[12];

    PFN_tmeTiled fn = nullptr;
    cudaDriverEntryPointQueryResult qres;
    cudaGetDriverEntryPoint("cuTensorMapEncodeTiled", (void**)&fn,
                            cudaEnableDefault, &qres);

    CUtensorMap tmE, tmS, tmR;
    encode_bias_map(fn, &tmE, edge);
    encode_bias_map(fn, &tmS, spat);
    encode_bias_map(fn, &tmR, rnk);

    cudaFuncSetAttribute(attn_tc_kernel,
                         cudaFuncAttributeMaxDynamicSharedMemorySize,
                         ATTN_SMEM_BYTES);
    cudaFuncSetAttribute(gemm_qkv_tc,
                         cudaFuncAttributeMaxDynamicSharedMemorySize,
                         GEMM_SMEM_BYTES);
    cudaFuncSetAttribute(gemm_o_tc,
                         cudaFuncAttributeMaxDynamicSharedMemorySize,
                         GEMM_SMEM_BYTES);

    gemm_qkv_tc<<<dim3(32, 4, 3), 256, GEMM_SMEM_BYTES>>>(
        x, Wq, Wk, Wv, bq, bk, bv, mask);

    attn_tc_kernel<<<dim3(16, 32), 128, ATTN_SMEM_BYTES>>>(tmE, tmS, tmR);

    gemm_o_tc<<<dim3(32, 4), 256, GEMM_SMEM_BYTES>>>(Wo, bo, (float*)d_out);
}